// round 3
// baseline (speedup 1.0000x reference)
#include <cuda_runtime.h>

#define H_DIM 448
#define W_DIM 512
#define HWTOT (448 * 512)

// Scratch (allocation-free rule: __device__ globals)
__device__ float g_xr[448 * 128 * 512];   // x_r in [h][c][w] layout
__device__ int   g_inds[448 * 512];       // argmax per pixel, (h,w) flat

__device__ __forceinline__ unsigned long long ffma2(unsigned long long a,
                                                    unsigned long long b,
                                                    unsigned long long c) {
    unsigned long long d;
    asm("fma.rn.f32x2 %0, %1, %2, %3;" : "=l"(d) : "l"(a), "l"(b), "l"(c));
    return d;
}
__device__ __forceinline__ unsigned long long dup2(float v) {
    unsigned long long d;
    asm("mov.b64 %0, {%1, %1};" : "=l"(d) : "f"(v));
    return d;
}
__device__ __forceinline__ float2 unpk(unsigned long long v) {
    float2 r;
    asm("mov.b64 {%0, %1}, %2;" : "=f"(r.x), "=f"(r.y) : "l"(v));
    return r;
}
__device__ __forceinline__ float lrelu(float v) { return v >= 0.0f ? v : 0.01f * v; }

// dst[o][w] = act( sum_c Wg[o*128+c] * src[c][w] + bg[o] ), 128x128x128.
// src/dst are smem float arrays with row stride 132 (16B-aligned rows).
// wsh: 2048-float smem staging (2 x 8k x 128o chunks, double buffered).
// 256 threads: ty=tid/16 -> o tiles {ty*4..+3, 64+ty*4..+3},
//              tx=tid%16 -> w tiles {tx*4..+3, 64+tx*4..+3}.
template <bool RELU>
__device__ void gemm128(const float* __restrict__ Wg, const float* __restrict__ bg,
                        const float* __restrict__ src, float* __restrict__ dst,
                        float* __restrict__ wsh, int tid)
{
    const int ty  = tid >> 4, tx = tid & 15;
    const int olo = ty << 2,  wlo = tx << 2;
    const int ldo = tid >> 1;          // o-row this thread loads
    const int ldk = (tid & 1) << 2;    // k offset 0 or 4 within chunk

    unsigned long long acc[8][4];
#pragma unroll
    for (int i = 0; i < 8; i++)
#pragma unroll
        for (int j = 0; j < 4; j++) acc[i][j] = 0ULL;

    // stage chunk 0 (transpose [o][k] -> wsh[k][o])
    float4 nxt = *(const float4*)&Wg[ldo * 128 + ldk];
    wsh[(ldk + 0) * 128 + ldo] = nxt.x;
    wsh[(ldk + 1) * 128 + ldo] = nxt.y;
    wsh[(ldk + 2) * 128 + ldo] = nxt.z;
    wsh[(ldk + 3) * 128 + ldo] = nxt.w;
    __syncthreads();

    for (int ch = 0; ch < 16; ch++) {
        const float* ws = wsh + ((ch & 1) << 10);
        if (ch < 15) nxt = *(const float4*)&Wg[ldo * 128 + (ch + 1) * 8 + ldk];
#pragma unroll
        for (int kk = 0; kk < 8; kk++) {
            const int k = (ch << 3) + kk;
            ulonglong2 a01 = *(const ulonglong2*)&src[k * 132 + wlo];
            ulonglong2 a23 = *(const ulonglong2*)&src[k * 132 + wlo + 64];
            float4 wa = *(const float4*)&ws[(kk << 7) + olo];
            float4 wb = *(const float4*)&ws[(kk << 7) + olo + 64];
            float wv[8] = {wa.x, wa.y, wa.z, wa.w, wb.x, wb.y, wb.z, wb.w};
#pragma unroll
            for (int o = 0; o < 8; o++) {
                unsigned long long wp = dup2(wv[o]);
                acc[o][0] = ffma2(a01.x, wp, acc[o][0]);
                acc[o][1] = ffma2(a01.y, wp, acc[o][1]);
                acc[o][2] = ffma2(a23.x, wp, acc[o][2]);
                acc[o][3] = ffma2(a23.y, wp, acc[o][3]);
            }
        }
        if (ch < 15) {
            float* wd = wsh + (((ch + 1) & 1) << 10);
            wd[(ldk + 0) * 128 + ldo] = nxt.x;
            wd[(ldk + 1) * 128 + ldo] = nxt.y;
            wd[(ldk + 2) * 128 + ldo] = nxt.z;
            wd[(ldk + 3) * 128 + ldo] = nxt.w;
        }
        __syncthreads();
    }

#pragma unroll
    for (int oo = 0; oo < 8; oo++) {
        const int o = (oo < 4) ? (olo + oo) : (64 + olo + oo - 4);
        const float b = bg[o];
        float2 v0 = unpk(acc[oo][0]);
        float2 v1 = unpk(acc[oo][1]);
        float2 v2 = unpk(acc[oo][2]);
        float2 v3 = unpk(acc[oo][3]);
        float r0 = v0.x + b, r1 = v0.y + b, r2 = v1.x + b, r3 = v1.y + b;
        float r4 = v2.x + b, r5 = v2.y + b, r6 = v3.x + b, r7 = v3.y + b;
        if (RELU) {
            r0 = lrelu(r0); r1 = lrelu(r1); r2 = lrelu(r2); r3 = lrelu(r3);
            r4 = lrelu(r4); r5 = lrelu(r5); r6 = lrelu(r6); r7 = lrelu(r7);
        }
        float4 lo4 = {r0, r1, r2, r3};
        float4 hi4 = {r4, r5, r6, r7};
        *(float4*)&dst[o * 132 + wlo]      = lo4;
        *(float4*)&dst[o * 132 + wlo + 64] = hi4;
    }
    __syncthreads();
}

// K1: per (wtile, h): classifier chain + mask + argmax + x_r.
__global__ void __launch_bounds__(256, 1)
k1_kernel(const float* __restrict__ x_in,
          const float* __restrict__ w_cl1, const float* __restrict__ b_cl1,
          const float* __restrict__ w_cl2, const float* __restrict__ b_cl2,
          const float* __restrict__ w_cl3, const float* __restrict__ b_cl3,
          const float* __restrict__ w_reg1, const float* __restrict__ b_reg1,
          float* __restrict__ out)
{
    extern __shared__ float smem[];
    float* bufX = smem;            // 128 x 132
    float* bufT = smem + 16896;    // 128 x 132
    float* bufU = smem + 33792;    // 128 x 132
    float* wsh  = smem + 50688;    // 2 x 8 x 128

    const int tid = threadIdx.x;
    const int wt = blockIdx.x, h = blockIdx.y;

    // load x tile: x[h][c][w] = x_in[c][h][w]
    const float* xsrc = x_in + h * W_DIM + wt * 128;
    for (int i = tid; i < 4096; i += 256) {
        int c = i >> 5, w4 = (i & 31) << 2;
        *(float4*)&bufX[c * 132 + w4] = *(const float4*)&xsrc[c * HWTOT + w4];
    }
    __syncthreads();

    gemm128<true >(w_cl1 + h * 16384, b_cl1 + h * 128, bufX, bufT, wsh, tid);
    gemm128<true >(w_cl2 + h * 16384, b_cl2 + h * 128, bufT, bufU, wsh, tid);
    gemm128<false>(w_cl3 + h * 16512, b_cl3 + h * 129, bufU, bufT, wsh, tid);  // logits

    // mask row: o = 128 of w_cl3, input = t2 (bufU)
    if (tid < 128) wsh[tid] = w_cl3[h * 16512 + 16384 + tid];
    __syncthreads();
    if (tid < 128) {
        float acc = b_cl3[h * 129 + 128];
#pragma unroll 8
        for (int c = 0; c < 128; c++) acc = fmaf(wsh[c], bufU[c * 132 + tid], acc);
        out[HWTOT + h * W_DIM + wt * 128 + tid] = lrelu(acc);
    }

    // argmax over logits (first-max-on-tie, like jnp.argmax)
    {
        const int col = tid >> 1, p = tid & 1;
        const int cbase = p << 6;
        float best = -1e30f; int bidx = 0;
#pragma unroll 8
        for (int i = 0; i < 64; i++) {
            float v = bufT[(cbase + i) * 132 + col];
            if (v > best) { best = v; bidx = cbase + i; }
        }
        float ob = __shfl_xor_sync(0xffffffffu, best, 1);
        int   oi = __shfl_xor_sync(0xffffffffu, bidx, 1);
        if (ob > best || (ob == best && oi < bidx)) bidx = oi;
        if (p == 0) g_inds[h * W_DIM + wt * 128 + col] = bidx;
    }
    __syncthreads();   // protect wsh before gemm4 restages it

    gemm128<true>(w_reg1 + h * 16384, b_reg1 + h * 128, bufX, bufU, wsh, tid);  // x_r

    // write x_r to scratch, [h][c][w] layout (coalesced)
    for (int i = tid; i < 4096; i += 256) {
        int o = i >> 5, w4 = (i & 31) << 2;
        *(float4*)&g_xr[(h * 128 + o) * W_DIM + wt * 128 + w4] =
            *(float4*)&bufU[o * 132 + w4];
    }
}

// K2: gathered regressor head + final output. Replicates the reference's
// cross-pixel index pairing: pixel (h,w) uses weights w2[g_inds[n] + (n/512)*128]
// with n = w*448 + h, but its OWN x_r row and OWN argmax in the final sum.
__global__ void __launch_bounds__(256)
k2_kernel(const float* __restrict__ w2, const float* __restrict__ b2,
          const float* __restrict__ w3, const float* __restrict__ b3,
          float* __restrict__ out)
{
    extern __shared__ float smem[];
    float* sxr = smem;  // [128 w][132] (c contiguous per pixel)
    const int tid = threadIdx.x;
    const int wt = blockIdx.x, h = blockIdx.y;

    for (int i = tid; i < 4096; i += 256) {
        int c = i >> 5, w4 = (i & 31) << 2;
        float4 v = *(const float4*)&g_xr[(h * 128 + c) * W_DIM + wt * 128 + w4];
        sxr[(w4 + 0) * 132 + c] = v.x;
        sxr[(w4 + 1) * 132 + c] = v.y;
        sxr[(w4 + 2) * 132 + c] = v.z;
        sxr[(w4 + 3) * 132 + c] = v.w;
    }
    __syncthreads();

    const int col = tid >> 1, p = tid & 1;
    const int wg = wt * 128 + col;
    const int n = wg * H_DIM + h;                  // rows/flattening order (w,h)
    const int ind_r = g_inds[n] + (n >> 9) * 128;  // inds_r[n]

    const float4* w2base = (const float4*)(w2 + (size_t)ind_r * 512) + (p << 6);
    const float* xr = &sxr[col * 132 + (p << 6)];

    float ax = 0.f, ay = 0.f, az = 0.f, aw = 0.f;
#pragma unroll
    for (int c4 = 0; c4 < 16; c4++) {
        float4 xv = *(const float4*)&xr[c4 << 2];
        float4 q0 = w2base[(c4 << 2) + 0];
        float4 q1 = w2base[(c4 << 2) + 1];
        float4 q2 = w2base[(c4 << 2) + 2];
        float4 q3 = w2base[(c4 << 2) + 3];
        ax = fmaf(xv.x, q0.x, fmaf(xv.y, q1.x, fmaf(xv.z, q2.x, fmaf(xv.w, q3.x, ax))));
        ay = fmaf(xv.x, q0.y, fmaf(xv.y, q1.y, fmaf(xv.z, q2.y, fmaf(xv.w, q3.y, ay))));
        az = fmaf(xv.x, q0.z, fmaf(xv.y, q1.z, fmaf(xv.z, q2.z, fmaf(xv.w, q3.z, az))));
        aw = fmaf(xv.x, q0.w, fmaf(xv.y, q1.w, fmaf(xv.z, q2.w, fmaf(xv.w, q3.w, aw))));
    }
    ax += __shfl_xor_sync(0xffffffffu, ax, 1);
    ay += __shfl_xor_sync(0xffffffffu, ay, 1);
    az += __shfl_xor_sync(0xffffffffu, az, 1);
    aw += __shfl_xor_sync(0xffffffffu, aw, 1);

    if (p == 0) {
        float4 b2v = *(const float4*)&b2[ind_r * 4];
        float h0 = lrelu(ax + b2v.x);
        float h1 = lrelu(ay + b2v.y);
        float h2 = lrelu(az + b2v.z);
        float h3 = lrelu(aw + b2v.w);
        float4 w3v = *(const float4*)&w3[ind_r * 4];
        float r = fmaf(h0, w3v.x, fmaf(h1, w3v.y, fmaf(h2, w3v.z,
                  fmaf(h3, w3v.w, b3[ind_r]))));
        int ind_self = g_inds[h * W_DIM + wg];
        out[h * W_DIM + wg] = ((float)ind_self + r) * (1.0f / 128.0f);
    }
}

extern "C" void kernel_launch(void* const* d_in, const int* in_sizes, int n_in,
                              void* d_out, int out_size)
{
    const float* x_in   = (const float*)d_in[0];
    const float* w_cl1  = (const float*)d_in[1];
    const float* b_cl1  = (const float*)d_in[2];
    const float* w_cl2  = (const float*)d_in[3];
    const float* b_cl2  = (const float*)d_in[4];
    const float* w_cl3  = (const float*)d_in[5];
    const float* b_cl3  = (const float*)d_in[6];
    const float* w_reg1 = (const float*)d_in[7];
    const float* b_reg1 = (const float*)d_in[8];
    const float* w2     = (const float*)d_in[9];
    const float* b2     = (const float*)d_in[10];
    const float* w3     = (const float*)d_in[11];
    const float* b3     = (const float*)d_in[12];
    float* out = (float*)d_out;

    const int smem1 = 52736 * 4;   // 210944 B
    const int smem2 = 16896 * 4;   // 67584 B
    cudaFuncSetAttribute(k1_kernel, cudaFuncAttributeMaxDynamicSharedMemorySize, smem1);
    cudaFuncSetAttribute(k2_kernel, cudaFuncAttributeMaxDynamicSharedMemorySize, smem2);

    dim3 grid(4, H_DIM);
    k1_kernel<<<grid, 256, smem1>>>(x_in, w_cl1, b_cl1, w_cl2, b_cl2,
                                    w_cl3, b_cl3, w_reg1, b_reg1, out);
    k2_kernel<<<grid, 256, smem2>>>(w2, b2, w3, b3, out);
}

// round 6
// speedup vs baseline: 1.1063x; 1.1063x over previous
#include <cuda_runtime.h>

#define H_DIM 448
#define W_DIM 512
#define HWTOT (448 * 512)

// Scratch (allocation-free rule: __device__ globals)
__device__ float g_xr[448 * 128 * 512];   // x_r in [h][c][w] layout
__device__ int   g_inds[448 * 512];       // argmax per pixel, (h,w) flat

__device__ __forceinline__ unsigned long long ffma2(unsigned long long a,
                                                    unsigned long long b,
                                                    unsigned long long c) {
    unsigned long long d;
    asm("fma.rn.f32x2 %0, %1, %2, %3;" : "=l"(d) : "l"(a), "l"(b), "l"(c));
    return d;
}
__device__ __forceinline__ unsigned long long dup2(float v) {
    unsigned long long d;
    asm("mov.b64 %0, {%1, %1};" : "=l"(d) : "f"(v));
    return d;
}
__device__ __forceinline__ float2 unpk(unsigned long long v) {
    float2 r;
    asm("mov.b64 {%0, %1}, %2;" : "=f"(r.x), "=f"(r.y) : "l"(v));
    return r;
}
__device__ __forceinline__ float lrelu(float v) { return v >= 0.0f ? v : 0.01f * v; }

// dst[o][w] = act( sum_c Wg[o*128+c] * src[c][w] + bg[o] ), 128x128x128.
// src/dst: smem arrays, row stride 132. wsh: 2x(8k x 128o) double-buffered.
// 512 threads: ty=tid/16 (32 o-groups of 4), tx=tid%16 (w = tx*4 + {0..3, 64..67}).
template <bool RELU>
__device__ void gemm128(const float* __restrict__ Wg, const float* __restrict__ bg,
                        const float* __restrict__ src, float* __restrict__ dst,
                        float* __restrict__ wsh, int tid)
{
    const int ty  = tid >> 4, tx = tid & 15;
    const int olo = ty << 2,  wlo = tx << 2;
    const int ldo = tid >> 2;          // o-row this thread stages (0..127)
    const int ldk = (tid & 3) << 1;    // k offset 0,2,4,6 within chunk

    unsigned long long acc[4][4];
#pragma unroll
    for (int i = 0; i < 4; i++)
#pragma unroll
        for (int j = 0; j < 4; j++) acc[i][j] = 0ULL;

    // stage chunk 0 (transpose [o][k] -> wsh[k][o])
    float2 nxt = *(const float2*)&Wg[ldo * 128 + ldk];
    wsh[(ldk + 0) * 128 + ldo] = nxt.x;
    wsh[(ldk + 1) * 128 + ldo] = nxt.y;
    __syncthreads();

    for (int ch = 0; ch < 16; ch++) {
        const float* ws = wsh + ((ch & 1) << 10);
        if (ch < 15) nxt = *(const float2*)&Wg[ldo * 128 + (ch + 1) * 8 + ldk];
#pragma unroll
        for (int kk = 0; kk < 8; kk++) {
            const int k = (ch << 3) + kk;
            ulonglong2 a01 = *(const ulonglong2*)&src[k * 132 + wlo];
            ulonglong2 a23 = *(const ulonglong2*)&src[k * 132 + wlo + 64];
            float4 wa = *(const float4*)&ws[(kk << 7) + olo];
            unsigned long long w0 = dup2(wa.x), w1 = dup2(wa.y);
            unsigned long long w2 = dup2(wa.z), w3 = dup2(wa.w);
            acc[0][0] = ffma2(a01.x, w0, acc[0][0]);
            acc[0][1] = ffma2(a01.y, w0, acc[0][1]);
            acc[0][2] = ffma2(a23.x, w0, acc[0][2]);
            acc[0][3] = ffma2(a23.y, w0, acc[0][3]);
            acc[1][0] = ffma2(a01.x, w1, acc[1][0]);
            acc[1][1] = ffma2(a01.y, w1, acc[1][1]);
            acc[1][2] = ffma2(a23.x, w1, acc[1][2]);
            acc[1][3] = ffma2(a23.y, w1, acc[1][3]);
            acc[2][0] = ffma2(a01.x, w2, acc[2][0]);
            acc[2][1] = ffma2(a01.y, w2, acc[2][1]);
            acc[2][2] = ffma2(a23.x, w2, acc[2][2]);
            acc[2][3] = ffma2(a23.y, w2, acc[2][3]);
            acc[3][0] = ffma2(a01.x, w3, acc[3][0]);
            acc[3][1] = ffma2(a01.y, w3, acc[3][1]);
            acc[3][2] = ffma2(a23.x, w3, acc[3][2]);
            acc[3][3] = ffma2(a23.y, w3, acc[3][3]);
        }
        if (ch < 15) {
            float* wd = wsh + (((ch + 1) & 1) << 10);
            wd[(ldk + 0) * 128 + ldo] = nxt.x;
            wd[(ldk + 1) * 128 + ldo] = nxt.y;
        }
        __syncthreads();
    }

#pragma unroll
    for (int oo = 0; oo < 4; oo++) {
        const int o = olo + oo;
        const float b = bg[o];
        float2 v0 = unpk(acc[oo][0]);
        float2 v1 = unpk(acc[oo][1]);
        float2 v2 = unpk(acc[oo][2]);
        float2 v3 = unpk(acc[oo][3]);
        float r0 = v0.x + b, r1 = v0.y + b, r2 = v1.x + b, r3 = v1.y + b;
        float r4 = v2.x + b, r5 = v2.y + b, r6 = v3.x + b, r7 = v3.y + b;
        if (RELU) {
            r0 = lrelu(r0); r1 = lrelu(r1); r2 = lrelu(r2); r3 = lrelu(r3);
            r4 = lrelu(r4); r5 = lrelu(r5); r6 = lrelu(r6); r7 = lrelu(r7);
        }
        float4 lo4 = {r0, r1, r2, r3};
        float4 hi4 = {r4, r5, r6, r7};
        *(float4*)&dst[o * 132 + wlo]      = lo4;
        *(float4*)&dst[o * 132 + wlo + 64] = hi4;
    }
    __syncthreads();
}

// K1: per (wtile, h): classifier chain + mask + argmax + x_r.
__global__ void __launch_bounds__(512, 1)
k1_kernel(const float* __restrict__ x_in,
          const float* __restrict__ w_cl1, const float* __restrict__ b_cl1,
          const float* __restrict__ w_cl2, const float* __restrict__ b_cl2,
          const float* __restrict__ w_cl3, const float* __restrict__ b_cl3,
          const float* __restrict__ w_reg1, const float* __restrict__ b_reg1,
          float* __restrict__ out)
{
    extern __shared__ float smem[];
    float* bufX = smem;            // 128 x 132
    float* bufT = smem + 16896;    // 128 x 132
    float* bufU = smem + 33792;    // 128 x 132
    float* wsh  = smem + 50688;    // 2 x 8 x 128

    const int tid = threadIdx.x;
    const int wt = blockIdx.x, h = blockIdx.y;

    // load x tile: x[h][c][w] = x_in[c][h][w]
    const float* xsrc = x_in + h * W_DIM + wt * 128;
    for (int i = tid; i < 4096; i += 512) {
        int c = i >> 5, w4 = (i & 31) << 2;
        *(float4*)&bufX[c * 132 + w4] = *(const float4*)&xsrc[c * HWTOT + w4];
    }
    __syncthreads();

    gemm128<true >(w_cl1 + h * 16384, b_cl1 + h * 128, bufX, bufT, wsh, tid);
    gemm128<true >(w_cl2 + h * 16384, b_cl2 + h * 128, bufT, bufU, wsh, tid);
    gemm128<false>(w_cl3 + h * 16512, b_cl3 + h * 129, bufU, bufT, wsh, tid);  // logits

    // mask row: o = 128 of w_cl3, input = t2 (bufU)
    if (tid < 128) wsh[tid] = w_cl3[h * 16512 + 16384 + tid];
    __syncthreads();
    if (tid < 128) {
        float acc = b_cl3[h * 129 + 128];
#pragma unroll 8
        for (int c = 0; c < 128; c++) acc = fmaf(wsh[c], bufU[c * 132 + tid], acc);
        out[HWTOT + h * W_DIM + wt * 128 + tid] = lrelu(acc);
    }

    // argmax over logits (first-max-on-tie, like jnp.argmax)
    if (tid < 256) {
        const int col = tid >> 1, p = tid & 1;
        const int cbase = p << 6;
        float best = -1e30f; int bidx = 0;
#pragma unroll 8
        for (int i = 0; i < 64; i++) {
            float v = bufT[(cbase + i) * 132 + col];
            if (v > best) { best = v; bidx = cbase + i; }
        }
        float ob = __shfl_xor_sync(0xffffffffu, best, 1);
        int   oi = __shfl_xor_sync(0xffffffffu, bidx, 1);
        if (ob > best || (ob == best && oi < bidx)) bidx = oi;
        if (p == 0) g_inds[h * W_DIM + wt * 128 + col] = bidx;
    }
    __syncthreads();   // protect wsh/bufU before reg1 gemm

    gemm128<true>(w_reg1 + h * 16384, b_reg1 + h * 128, bufX, bufU, wsh, tid);  // x_r

    // write x_r to scratch, [h][c][w] layout (coalesced)
    for (int i = tid; i < 4096; i += 512) {
        int o = i >> 5, w4 = (i & 31) << 2;
        *(float4*)&g_xr[(h * 128 + o) * W_DIM + wt * 128 + w4] =
            *(float4*)&bufU[o * 132 + w4];
    }
}

// K2: gathered regressor head + final output. One warp per pixel:
// lane l loads w2[ind][c=j*32+l][0..3] as a coalesced float4 burst.
// Cross-pixel pairing per reference: pixel (h,w) uses w2[inds_r[n]],
// n = w*448 + h, but its OWN x_r row and OWN argmax in the final sum.
__global__ void __launch_bounds__(256)
k2_kernel(const float* __restrict__ w2, const float* __restrict__ b2,
          const float* __restrict__ w3, const float* __restrict__ b3,
          float* __restrict__ out)
{
    extern __shared__ float smem[];
    float* sxr    = smem;                    // [128 w][132] (c contiguous per pixel)
    int*   s_indr = (int*)(smem + 16896);    // 128
    int*   s_self = (int*)(smem + 16896 + 128);

    const int tid = threadIdx.x;
    const int wt = blockIdx.x, h = blockIdx.y;

    for (int i = tid; i < 4096; i += 256) {
        int c = i >> 5, w4 = (i & 31) << 2;
        float4 v = *(const float4*)&g_xr[(h * 128 + c) * W_DIM + wt * 128 + w4];
        sxr[(w4 + 0) * 132 + c] = v.x;
        sxr[(w4 + 1) * 132 + c] = v.y;
        sxr[(w4 + 2) * 132 + c] = v.z;
        sxr[(w4 + 3) * 132 + c] = v.w;
    }
    if (tid < 128) {
        int wg = wt * 128 + tid;
        int n = wg * H_DIM + h;                  // flattening order (w,h)
        s_indr[tid] = g_inds[n] + (n >> 9) * 128;
        s_self[tid] = g_inds[h * W_DIM + wg];
    }
    __syncthreads();

    const int warp = tid >> 5, lane = tid & 31;

    for (int i = 0; i < 16; i++) {
        const int wloc = warp * 16 + i;
        const int ind_r = s_indr[wloc];
        const float4* w2p = (const float4*)(w2 + (size_t)ind_r * 512);

        float ax = 0.f, ay = 0.f, az = 0.f, aw = 0.f;
#pragma unroll
        for (int j = 0; j < 4; j++) {
            float4 q = w2p[(j << 5) + lane];                 // coalesced 512B/warp
            float xv = sxr[wloc * 132 + (j << 5) + lane];    // conflict-free
            ax = fmaf(xv, q.x, ax);
            ay = fmaf(xv, q.y, ay);
            az = fmaf(xv, q.z, az);
            aw = fmaf(xv, q.w, aw);
        }
#pragma unroll
        for (int off = 16; off; off >>= 1) {
            ax += __shfl_xor_sync(0xffffffffu, ax, off);
            ay += __shfl_xor_sync(0xffffffffu, ay, off);
            az += __shfl_xor_sync(0xffffffffu, az, off);
            aw += __shfl_xor_sync(0xffffffffu, aw, off);
        }
        if (lane == 0) {
            float4 b2v = *(const float4*)&b2[ind_r * 4];
            float h0 = lrelu(ax + b2v.x);
            float h1 = lrelu(ay + b2v.y);
            float h2 = lrelu(az + b2v.z);
            float h3 = lrelu(aw + b2v.w);
            float4 w3v = *(const float4*)&w3[ind_r * 4];
            float r = fmaf(h0, w3v.x, fmaf(h1, w3v.y, fmaf(h2, w3v.z,
                      fmaf(h3, w3v.w, b3[ind_r]))));
            out[h * W_DIM + wt * 128 + wloc] =
                ((float)s_self[wloc] + r) * (1.0f / 128.0f);
        }
    }
}

extern "C" void kernel_launch(void* const* d_in, const int* in_sizes, int n_in,
                              void* d_out, int out_size)
{
    const float* x_in   = (const float*)d_in[0];
    const float* w_cl1  = (const float*)d_in[1];
    const float* b_cl1  = (const float*)d_in[2];
    const float* w_cl2  = (const float*)d_in[3];
    const float* b_cl2  = (const float*)d_in[4];
    const float* w_cl3  = (const float*)d_in[5];
    const float* b_cl3  = (const float*)d_in[6];
    const float* w_reg1 = (const float*)d_in[7];
    const float* b_reg1 = (const float*)d_in[8];
    const float* w2     = (const float*)d_in[9];
    const float* b2     = (const float*)d_in[10];
    const float* w3     = (const float*)d_in[11];
    const float* b3     = (const float*)d_in[12];
    float* out = (float*)d_out;

    const int smem1 = 52736 * 4;                // 210944 B
    const int smem2 = (16896 + 256) * 4;        // 68608 B
    cudaFuncSetAttribute(k1_kernel, cudaFuncAttributeMaxDynamicSharedMemorySize, smem1);
    cudaFuncSetAttribute(k2_kernel, cudaFuncAttributeMaxDynamicSharedMemorySize, smem2);

    dim3 grid(4, H_DIM);
    k1_kernel<<<grid, 512, smem1>>>(x_in, w_cl1, b_cl1, w_cl2, b_cl2,
                                    w_cl3, b_cl3, w_reg1, b_reg1, out);
    k2_kernel<<<grid, 256, smem2>>>(w2, b2, w3, b3, out);
}

// round 9
// speedup vs baseline: 1.1092x; 1.0026x over previous
#include <cuda_runtime.h>

#define H_DIM 448
#define W_DIM 512
#define HWTOT (448 * 512)

// Scratch (allocation-free rule: __device__ globals)
__device__ float g_xr[448 * 128 * 512];   // x_r in [h][c][w] layout
__device__ int   g_inds[448 * 512];       // argmax per pixel, (h,w) flat

__device__ __forceinline__ unsigned long long ffma2(unsigned long long a,
                                                    unsigned long long b,
                                                    unsigned long long c) {
    unsigned long long d;
    asm("fma.rn.f32x2 %0, %1, %2, %3;" : "=l"(d) : "l"(a), "l"(b), "l"(c));
    return d;
}
__device__ __forceinline__ unsigned long long dup2(float v) {
    unsigned long long d;
    asm("mov.b64 %0, {%1, %1};" : "=l"(d) : "f"(v));
    return d;
}
__device__ __forceinline__ float2 unpk(unsigned long long v) {
    float2 r;
    asm("mov.b64 {%0, %1}, %2;" : "=f"(r.x), "=f"(r.y) : "l"(v));
    return r;
}
__device__ __forceinline__ float lrelu(float v) { return v >= 0.0f ? v : 0.01f * v; }

// dst[o][w] = act( sum_c Wg[o*128+c] * src[c][w] + bg[o] ), 128x128x128.
// src/dst: smem arrays, row stride 132. wsh: 2x(8k x 128o) double-buffered.
// 512 threads: ty=tid/16 (32 o-groups of 4), tx=tid%16 (w = tx*4 + {0..3, 64..67}).
template <bool RELU>
__device__ void gemm128(const float* __restrict__ Wg, const float* __restrict__ bg,
                        const float* __restrict__ src, float* __restrict__ dst,
                        float* __restrict__ wsh, int tid)
{
    const int ty  = tid >> 4, tx = tid & 15;
    const int olo = ty << 2,  wlo = tx << 2;
    const int ldo = tid >> 2;          // o-row this thread stages (0..127)
    const int ldk = (tid & 3) << 1;    // k offset 0,2,4,6 within chunk

    unsigned long long acc[4][4];
#pragma unroll
    for (int i = 0; i < 4; i++)
#pragma unroll
        for (int j = 0; j < 4; j++) acc[i][j] = 0ULL;

    // stage chunk 0 (transpose [o][k] -> wsh[k][o])
    float2 nxt = *(const float2*)&Wg[ldo * 128 + ldk];
    wsh[(ldk + 0) * 128 + ldo] = nxt.x;
    wsh[(ldk + 1) * 128 + ldo] = nxt.y;
    __syncthreads();

    for (int ch = 0; ch < 16; ch++) {
        const float* ws = wsh + ((ch & 1) << 10);
        if (ch < 15) nxt = *(const float2*)&Wg[ldo * 128 + (ch + 1) * 8 + ldk];
#pragma unroll
        for (int kk = 0; kk < 8; kk++) {
            const int k = (ch << 3) + kk;
            ulonglong2 a01 = *(const ulonglong2*)&src[k * 132 + wlo];
            ulonglong2 a23 = *(const ulonglong2*)&src[k * 132 + wlo + 64];
            float4 wa = *(const float4*)&ws[(kk << 7) + olo];
            unsigned long long w0 = dup2(wa.x), w1 = dup2(wa.y);
            unsigned long long w2 = dup2(wa.z), w3 = dup2(wa.w);
            acc[0][0] = ffma2(a01.x, w0, acc[0][0]);
            acc[0][1] = ffma2(a01.y, w0, acc[0][1]);
            acc[0][2] = ffma2(a23.x, w0, acc[0][2]);
            acc[0][3] = ffma2(a23.y, w0, acc[0][3]);
            acc[1][0] = ffma2(a01.x, w1, acc[1][0]);
            acc[1][1] = ffma2(a01.y, w1, acc[1][1]);
            acc[1][2] = ffma2(a23.x, w1, acc[1][2]);
            acc[1][3] = ffma2(a23.y, w1, acc[1][3]);
            acc[2][0] = ffma2(a01.x, w2, acc[2][0]);
            acc[2][1] = ffma2(a01.y, w2, acc[2][1]);
            acc[2][2] = ffma2(a23.x, w2, acc[2][2]);
            acc[2][3] = ffma2(a23.y, w2, acc[2][3]);
            acc[3][0] = ffma2(a01.x, w3, acc[3][0]);
            acc[3][1] = ffma2(a01.y, w3, acc[3][1]);
            acc[3][2] = ffma2(a23.x, w3, acc[3][2]);
            acc[3][3] = ffma2(a23.y, w3, acc[3][3]);
        }
        if (ch < 15) {
            float* wd = wsh + (((ch + 1) & 1) << 10);
            wd[(ldk + 0) * 128 + ldo] = nxt.x;
            wd[(ldk + 1) * 128 + ldo] = nxt.y;
        }
        __syncthreads();
    }

#pragma unroll
    for (int oo = 0; oo < 4; oo++) {
        const int o = olo + oo;
        const float b = bg[o];
        float2 v0 = unpk(acc[oo][0]);
        float2 v1 = unpk(acc[oo][1]);
        float2 v2 = unpk(acc[oo][2]);
        float2 v3 = unpk(acc[oo][3]);
        float r0 = v0.x + b, r1 = v0.y + b, r2 = v1.x + b, r3 = v1.y + b;
        float r4 = v2.x + b, r5 = v2.y + b, r6 = v3.x + b, r7 = v3.y + b;
        if (RELU) {
            r0 = lrelu(r0); r1 = lrelu(r1); r2 = lrelu(r2); r3 = lrelu(r3);
            r4 = lrelu(r4); r5 = lrelu(r5); r6 = lrelu(r6); r7 = lrelu(r7);
        }
        float4 lo4 = {r0, r1, r2, r3};
        float4 hi4 = {r4, r5, r6, r7};
        *(float4*)&dst[o * 132 + wlo]      = lo4;
        *(float4*)&dst[o * 132 + wlo + 64] = hi4;
    }
    __syncthreads();
}

// K1: per (wtile, h): classifier chain + mask + argmax + x_r.
__global__ void __launch_bounds__(512, 1)
k1_kernel(const float* __restrict__ x_in,
          const float* __restrict__ w_cl1, const float* __restrict__ b_cl1,
          const float* __restrict__ w_cl2, const float* __restrict__ b_cl2,
          const float* __restrict__ w_cl3, const float* __restrict__ b_cl3,
          const float* __restrict__ w_reg1, const float* __restrict__ b_reg1,
          float* __restrict__ out)
{
    extern __shared__ float smem[];
    float* bufX = smem;            // 128 x 132
    float* bufT = smem + 16896;    // 128 x 132
    float* bufU = smem + 33792;    // 128 x 132
    float* wsh  = smem + 50688;    // 2 x 8 x 128

    const int tid = threadIdx.x;
    const int wt = blockIdx.x, h = blockIdx.y;

    // load x tile: x[h][c][w] = x_in[c][h][w]
    const float* xsrc = x_in + h * W_DIM + wt * 128;
    for (int i = tid; i < 4096; i += 512) {
        int c = i >> 5, w4 = (i & 31) << 2;
        *(float4*)&bufX[c * 132 + w4] = *(const float4*)&xsrc[c * HWTOT + w4];
    }
    __syncthreads();

    gemm128<true >(w_cl1 + h * 16384, b_cl1 + h * 128, bufX, bufT, wsh, tid);
    gemm128<true >(w_cl2 + h * 16384, b_cl2 + h * 128, bufT, bufU, wsh, tid);
    gemm128<false>(w_cl3 + h * 16512, b_cl3 + h * 129, bufU, bufT, wsh, tid);  // logits

    // mask row: o = 128 of w_cl3, input = t2 (bufU)
    if (tid < 128) wsh[tid] = w_cl3[h * 16512 + 16384 + tid];
    __syncthreads();
    if (tid < 128) {
        float acc = b_cl3[h * 129 + 128];
#pragma unroll 8
        for (int c = 0; c < 128; c++) acc = fmaf(wsh[c], bufU[c * 132 + tid], acc);
        out[HWTOT + h * W_DIM + wt * 128 + tid] = lrelu(acc);
    }

    // argmax over logits (first-max-on-tie, like jnp.argmax)
    if (tid < 256) {
        const int col = tid >> 1, p = tid & 1;
        const int cbase = p << 6;
        float best = -1e30f; int bidx = 0;
#pragma unroll 8
        for (int i = 0; i < 64; i++) {
            float v = bufT[(cbase + i) * 132 + col];
            if (v > best) { best = v; bidx = cbase + i; }
        }
        float ob = __shfl_xor_sync(0xffffffffu, best, 1);
        int   oi = __shfl_xor_sync(0xffffffffu, bidx, 1);
        if (ob > best || (ob == best && oi < bidx)) bidx = oi;
        if (p == 0) g_inds[h * W_DIM + wt * 128 + col] = bidx;
    }
    __syncthreads();   // protect wsh/bufU before reg1 gemm

    gemm128<true>(w_reg1 + h * 16384, b_reg1 + h * 128, bufX, bufU, wsh, tid);  // x_r

    // write x_r to scratch, [h][c][w] layout (coalesced)
    for (int i = tid; i < 4096; i += 512) {
        int o = i >> 5, w4 = (i & 31) << 2;
        *(float4*)&g_xr[(h * 128 + o) * W_DIM + wt * 128 + w4] =
            *(float4*)&bufU[o * 132 + w4];
    }
}

// K2: gathered regressor head + final output. One warp per pixel:
// lane l loads w2[ind][c=j*32+l][0..3] as a coalesced float4 burst.
// Cross-pixel pairing per reference: pixel (h,w) uses w2[inds_r[n]],
// n = w*448 + h, but its OWN x_r row and OWN argmax in the final sum.
__global__ void __launch_bounds__(256)
k2_kernel(const float* __restrict__ w2, const float* __restrict__ b2,
          const float* __restrict__ w3, const float* __restrict__ b3,
          float* __restrict__ out)
{
    extern __shared__ float smem[];
    float* sxr    = smem;                    // [128 w][132] (c contiguous per pixel)
    int*   s_indr = (int*)(smem + 16896);    // 128
    int*   s_self = (int*)(smem + 16896 + 128);

    const int tid = threadIdx.x;
    const int wt = blockIdx.x, h = blockIdx.y;

    for (int i = tid; i < 4096; i += 256) {
        int c = i >> 5, w4 = (i & 31) << 2;
        float4 v = *(const float4*)&g_xr[(h * 128 + c) * W_DIM + wt * 128 + w4];
        sxr[(w4 + 0) * 132 + c] = v.x;
        sxr[(w4 + 1) * 132 + c] = v.y;
        sxr[(w4 + 2) * 132 + c] = v.z;
        sxr[(w4 + 3) * 132 + c] = v.w;
    }
    if (tid < 128) {
        int wg = wt * 128 + tid;
        int n = wg * H_DIM + h;                  // flattening order (w,h)
        s_indr[tid] = g_inds[n] + (n >> 9) * 128;
        s_self[tid] = g_inds[h * W_DIM + wg];
    }
    __syncthreads();

    const int warp = tid >> 5, lane = tid & 31;

    for (int i = 0; i < 16; i++) {
        const int wloc = warp * 16 + i;
        const int ind_r = s_indr[wloc];
        const float4* w2p = (const float4*)(w2 + (size_t)ind_r * 512);

        float ax = 0.f, ay = 0.f, az = 0.f, aw = 0.f;
#pragma unroll
        for (int j = 0; j < 4; j++) {
            float4 q = w2p[(j << 5) + lane];                 // coalesced 512B/warp
            float xv = sxr[wloc * 132 + (j << 5) + lane];    // conflict-free
            ax = fmaf(xv, q.x, ax);
            ay = fmaf(xv, q.y, ay);
            az = fmaf(xv, q.z, az);
            aw = fmaf(xv, q.w, aw);
        }
#pragma unroll
        for (int off = 16; off; off >>= 1) {
            ax += __shfl_xor_sync(0xffffffffu, ax, off);
            ay += __shfl_xor_sync(0xffffffffu, ay, off);
            az += __shfl_xor_sync(0xffffffffu, az, off);
            aw += __shfl_xor_sync(0xffffffffu, aw, off);
        }
        if (lane == 0) {
            float4 b2v = *(const float4*)&b2[ind_r * 4];
            float h0 = lrelu(ax + b2v.x);
            float h1 = lrelu(ay + b2v.y);
            float h2 = lrelu(az + b2v.z);
            float h3 = lrelu(aw + b2v.w);
            float4 w3v = *(const float4*)&w3[ind_r * 4];
            float r = fmaf(h0, w3v.x, fmaf(h1, w3v.y, fmaf(h2, w3v.z,
                      fmaf(h3, w3v.w, b3[ind_r]))));
            out[h * W_DIM + wt * 128 + wloc] =
                ((float)s_self[wloc] + r) * (1.0f / 128.0f);
        }
    }
}

extern "C" void kernel_launch(void* const* d_in, const int* in_sizes, int n_in,
                              void* d_out, int out_size)
{
    const float* x_in   = (const float*)d_in[0];
    const float* w_cl1  = (const float*)d_in[1];
    const float* b_cl1  = (const float*)d_in[2];
    const float* w_cl2  = (const float*)d_in[3];
    const float* b_cl2  = (const float*)d_in[4];
    const float* w_cl3  = (const float*)d_in[5];
    const float* b_cl3  = (const float*)d_in[6];
    const float* w_reg1 = (const float*)d_in[7];
    const float* b_reg1 = (const float*)d_in[8];
    const float* w2     = (const float*)d_in[9];
    const float* b2     = (const float*)d_in[10];
    const float* w3     = (const float*)d_in[11];
    const float* b3     = (const float*)d_in[12];
    float* out = (float*)d_out;

    const int smem1 = 52736 * 4;                // 210944 B
    const int smem2 = (16896 + 256) * 4;        // 68608 B
    cudaFuncSetAttribute(k1_kernel, cudaFuncAttributeMaxDynamicSharedMemorySize, smem1);
    cudaFuncSetAttribute(k2_kernel, cudaFuncAttributeMaxDynamicSharedMemorySize, smem2);

    dim3 grid(4, H_DIM);
    k1_kernel<<<grid, 512, smem1>>>(x_in, w_cl1, b_cl1, w_cl2, b_cl2,
                                    w_cl3, b_cl3, w_reg1, b_reg1, out);
    k2_kernel<<<grid, 256, smem2>>>(w2, b2, w3, b3, out);
}

// round 13
// speedup vs baseline: 1.1802x; 1.0639x over previous
#include <cuda_runtime.h>
#include <cstdint>

#define H_DIM 448
#define W_DIM 512
#define HWTOT (448 * 512)

// Scratch (allocation-free rule: __device__ globals)
__device__ float g_xr[448 * 128 * 512];   // x_r in [h][c][w] layout
__device__ int   g_inds[448 * 512];       // argmax per pixel, (h,w) flat

__device__ __forceinline__ float lrelu(float v) { return v >= 0.0f ? v : 0.01f * v; }
__device__ __forceinline__ uint32_t f2tf32(float v) {
    uint32_t r;
    asm("cvt.rna.tf32.f32 %0, %1;" : "=r"(r) : "f"(v));
    return r;
}

// m16n8k8 tf32 mma (sm_80 feature — compiles under compute_103)
__device__ __forceinline__ void mma8(float* d, uint4 a, uint2 b) {
    asm volatile(
        "mma.sync.aligned.m16n8k8.row.col.f32.tf32.tf32.f32 "
        "{%0,%1,%2,%3}, {%4,%5,%6,%7}, {%8,%9}, {%0,%1,%2,%3};"
        : "+f"(d[0]), "+f"(d[1]), "+f"(d[2]), "+f"(d[3])
        : "r"(a.x), "r"(a.y), "r"(a.z), "r"(a.w), "r"(b.x), "r"(b.y));
}

// ---------------- smem layout (bytes) ----------------
static constexpr int AFH_B   = 0;        // A-frag hi: 16ks x 8mt x 32lane x float4 = 64KB
static constexpr int AFL_B   = 65536;    // A-frag lo: 64KB
static constexpr int BF_B    = 131072;   // B-frag: 2 bufs x (hi 16KB + lo 16KB)
static constexpr int SBIAS_B = 196608;   // 128 f
static constexpr int SMROW_B = 197120;   // 128 f
static constexpr int SMP_B   = 197632;   // 4x128 f
static constexpr int SAV_B   = 199680;   // 4x128 f
static constexpr int SAI_B   = 201728;   // 4x128 i
static constexpr int SMEM1_B = 203776;

// write value v at (pixel R, channel C) into A-fragment hi/lo planes
__device__ __forceinline__ void af_write(float* aFh, float* aFl, int R, int C, float v) {
    int ks = C >> 3, mt = R >> 4, r = R & 15, c = C & 7;
    int slot = ((ks * 8 + mt) * 32 + (r & 7) * 4 + (c & 3)) * 4
             + ((r >> 3) & 1) + (((c >> 2) & 1) << 1);
    uint32_t hi = f2tf32(v);
    aFh[slot] = __uint_as_float(hi);
    aFl[slot] = __uint_as_float(f2tf32(v - __uint_as_float(hi)));
}

// stage one 32-channel chunk of W (prefetched in pre[2]) into B-frag buffers
__device__ __forceinline__ void stage_b(char* sm, int buf, const float4* pre, int tid) {
    char* hb = sm + BF_B + buf * 32768;
    char* lb = hb + 16384;
#pragma unroll
    for (int j = 0; j < 2; j++) {
        int idx = j * 512 + tid;
        int o = idx >> 3, c4 = idx & 7;
        int ksl = c4 >> 1, reg = c4 & 1, nt = o >> 3, l4 = (o & 7) * 4;
        float v[4] = {pre[j].x, pre[j].y, pre[j].z, pre[j].w};
#pragma unroll
        for (int e = 0; e < 4; e++) {
            int off = (((ksl * 16 + nt) * 32 + l4 + e) << 3) + (reg << 2);
            uint32_t hi = f2tf32(v[e]);
            *(float*)(hb + off) = __uint_as_float(hi);
            *(float*)(lb + off) = __uint_as_float(f2tf32(v[e] - __uint_as_float(hi)));
        }
    }
}

// EPI: 0 = reg1 (x_r -> gmem), 1 = cl1 (split -> A), 2 = cl2 (split -> A + mask),
//      3 = cl3 (argmax, no activation)
template <int EPI>
__device__ void run_gemm(const float* __restrict__ Wg, const float* __restrict__ bias,
                         const float* __restrict__ mrow, const float* __restrict__ mbias,
                         char* sm, float* __restrict__ out, int wt, int h, int tid)
{
    float* aFh   = (float*)(sm + AFH_B);
    float* aFl   = (float*)(sm + AFL_B);
    float* sBias = (float*)(sm + SBIAS_B);
    float* sMrow = (float*)(sm + SMROW_B);
    float* sMP   = (float*)(sm + SMP_B);
    float* sAV   = (float*)(sm + SAV_B);
    int*   sAI   = (int*)(sm + SAI_B);

    const int warp = tid >> 5, lane = tid & 31;
    const int mi = warp >> 2, ni = warp & 3;
    const int g = lane >> 2, t = lane & 3;

    __syncthreads();   // prior epilogue done before we touch sBias / bF

    if (tid < 128) sBias[tid] = bias[tid];
    if (EPI == 2 && tid < 128) sMrow[tid] = mrow[tid];

    // stage chunk 0
    {
        float4 pre[2];
#pragma unroll
        for (int j = 0; j < 2; j++) {
            int idx = j * 512 + tid;
            pre[j] = *(const float4*)&Wg[(idx >> 3) * 128 + (idx & 7) * 4];
        }
        stage_b(sm, 0, pre, tid);
    }
    __syncthreads();

    float acc[2][4][4];
#pragma unroll
    for (int a = 0; a < 2; a++)
#pragma unroll
        for (int b = 0; b < 4; b++)
#pragma unroll
            for (int c = 0; c < 4; c++) acc[a][b][c] = 0.0f;

    float4 pre[2];
    for (int ck = 0; ck < 4; ck++) {
        if (ck < 3) {
#pragma unroll
            for (int j = 0; j < 2; j++) {
                int idx = j * 512 + tid;
                pre[j] = *(const float4*)&Wg[(idx >> 3) * 128 + (ck + 1) * 32 + (idx & 7) * 4];
            }
        }
        const char* hb = sm + BF_B + (ck & 1) * 32768;
        const char* lb = hb + 16384;
#pragma unroll
        for (int ksl = 0; ksl < 4; ksl++) {
            const int ks = ck * 4 + ksl;
            uint4 ah[2], al[2];
#pragma unroll
            for (int m2 = 0; m2 < 2; m2++) {
                int aslot = (ks * 8 + 2 * mi + m2) * 32 + lane;
                ah[m2] = ((const uint4*)aFh)[aslot];
                al[m2] = ((const uint4*)aFl)[aslot];
            }
            uint2 bh[4], bl[4];
#pragma unroll
            for (int n4 = 0; n4 < 4; n4++) {
                int slot = ((ksl * 16 + ni * 4 + n4) * 32 + lane) << 3;
                bh[n4] = *(const uint2*)(hb + slot);
                bl[n4] = *(const uint2*)(lb + slot);
            }
#pragma unroll
            for (int m2 = 0; m2 < 2; m2++)
#pragma unroll
                for (int n4 = 0; n4 < 4; n4++) {
                    float* d = acc[m2][n4];
                    mma8(d, al[m2], bl[n4]);
                    mma8(d, ah[m2], bl[n4]);
                    mma8(d, al[m2], bh[n4]);
                    mma8(d, ah[m2], bh[n4]);
                }
        }
        if (ck < 3) stage_b(sm, (ck + 1) & 1, pre, tid);
        __syncthreads();
    }

    // ---------------- epilogue from D fragments ----------------
    if (EPI == 0) {
#pragma unroll
        for (int m2 = 0; m2 < 2; m2++)
#pragma unroll
            for (int n4 = 0; n4 < 4; n4++)
#pragma unroll
                for (int j = 0; j < 4; j++) {
                    int C = ni * 32 + n4 * 8 + 2 * t + (j & 1);
                    int R = mi * 32 + m2 * 16 + g + 8 * (j >> 1);
                    float v = lrelu(acc[m2][n4][j] + sBias[C]);
                    g_xr[(size_t)(h * 128 + C) * W_DIM + wt * 128 + R] = v;
                }
    } else if (EPI == 1 || EPI == 2) {
        float mp[2][2] = {{0.f, 0.f}, {0.f, 0.f}};
#pragma unroll
        for (int m2 = 0; m2 < 2; m2++)
#pragma unroll
            for (int n4 = 0; n4 < 4; n4++)
#pragma unroll
                for (int j = 0; j < 4; j++) {
                    int C = ni * 32 + n4 * 8 + 2 * t + (j & 1);
                    int R = mi * 32 + m2 * 16 + g + 8 * (j >> 1);
                    float v = lrelu(acc[m2][n4][j] + sBias[C]);
                    af_write(aFh, aFl, R, C, v);
                    if (EPI == 2) mp[m2][j >> 1] = fmaf(v, sMrow[C], mp[m2][j >> 1]);
                }
        if (EPI == 2) {
#pragma unroll
            for (int m2 = 0; m2 < 2; m2++)
#pragma unroll
                for (int rh = 0; rh < 2; rh++) {
                    mp[m2][rh] += __shfl_xor_sync(0xffffffffu, mp[m2][rh], 1);
                    mp[m2][rh] += __shfl_xor_sync(0xffffffffu, mp[m2][rh], 2);
                }
            if (t == 0) {
#pragma unroll
                for (int m2 = 0; m2 < 2; m2++)
#pragma unroll
                    for (int rh = 0; rh < 2; rh++) {
                        int R = mi * 32 + m2 * 16 + g + 8 * rh;
                        sMP[ni * 128 + R] = mp[m2][rh];
                    }
            }
            __syncthreads();
            if (tid < 128) {
                float m = sMP[tid] + sMP[128 + tid] + sMP[256 + tid] + sMP[384 + tid]
                        + __ldg(mbias);
                out[HWTOT + h * W_DIM + wt * 128 + tid] = lrelu(m);
            }
        }
    } else {  // EPI == 3: argmax (first-max-on-tie like jnp.argmax)
#pragma unroll
        for (int m2 = 0; m2 < 2; m2++)
#pragma unroll
            for (int rh = 0; rh < 2; rh++) {
                float bv = -3.4e38f; int bi = 0;
#pragma unroll
                for (int n4 = 0; n4 < 4; n4++)
#pragma unroll
                    for (int jb = 0; jb < 2; jb++) {
                        int C = ni * 32 + n4 * 8 + 2 * t + jb;
                        float v = acc[m2][n4][rh * 2 + jb] + sBias[C];
                        if (v > bv) { bv = v; bi = C; }
                    }
#pragma unroll
                for (int off = 1; off <= 2; off <<= 1) {
                    float ov = __shfl_xor_sync(0xffffffffu, bv, off);
                    int   oi = __shfl_xor_sync(0xffffffffu, bi, off);
                    if (ov > bv || (ov == bv && oi < bi)) { bv = ov; bi = oi; }
                }
                if (t == 0) {
                    int R = mi * 32 + m2 * 16 + g + 8 * rh;
                    sAV[ni * 128 + R] = bv;
                    sAI[ni * 128 + R] = bi;
                }
            }
        __syncthreads();
        if (tid < 128) {
            float b = sAV[tid]; int x = sAI[tid];
#pragma unroll
            for (int q = 1; q < 4; q++) {
                float ov = sAV[q * 128 + tid];
                int   oi = sAI[q * 128 + tid];
                if (ov > b || (ov == b && oi < x)) { b = ov; x = oi; }
            }
            g_inds[h * W_DIM + wt * 128 + tid] = x;
        }
    }
}

// K1: per (wtile, h): x -> A-frags, then reg1, cl1, cl2(+mask), cl3(+argmax)
__global__ void __launch_bounds__(512, 1)
k1_kernel(const float* __restrict__ x_in,
          const float* __restrict__ w_cl1, const float* __restrict__ b_cl1,
          const float* __restrict__ w_cl2, const float* __restrict__ b_cl2,
          const float* __restrict__ w_cl3, const float* __restrict__ b_cl3,
          const float* __restrict__ w_reg1, const float* __restrict__ b_reg1,
          float* __restrict__ out)
{
    extern __shared__ char sm[];
    float* aFh = (float*)(sm + AFH_B);
    float* aFl = (float*)(sm + AFL_B);
    const int tid = threadIdx.x;
    const int wt = blockIdx.x, h = blockIdx.y;

    // stage x (coalesced gmem read, scatter into A-frag layout)
    const float* xsrc = x_in + (size_t)h * W_DIM + wt * 128;
#pragma unroll
    for (int j = 0; j < 8; j++) {
        int idx = j * 512 + tid;           // 4096 float4 total
        int c = idx >> 5, w4 = (idx & 31) << 2;
        float4 v = *(const float4*)&xsrc[(size_t)c * HWTOT + w4];
        af_write(aFh, aFl, w4 + 0, c, v.x);
        af_write(aFh, aFl, w4 + 1, c, v.y);
        af_write(aFh, aFl, w4 + 2, c, v.z);
        af_write(aFh, aFl, w4 + 3, c, v.w);
    }

    run_gemm<0>(w_reg1 + h * 16384, b_reg1 + h * 128, nullptr, nullptr,
                sm, out, wt, h, tid);
    run_gemm<1>(w_cl1 + h * 16384, b_cl1 + h * 128, nullptr, nullptr,
                sm, out, wt, h, tid);
    run_gemm<2>(w_cl2 + h * 16384, b_cl2 + h * 128,
                w_cl3 + h * 16512 + 16384, b_cl3 + h * 129 + 128,
                sm, out, wt, h, tid);
    run_gemm<3>(w_cl3 + h * 16512, b_cl3 + h * 129, nullptr, nullptr,
                sm, out, wt, h, tid);
}

// K2: gathered regressor head + final output. One warp per pixel, 512 threads.
// Cross-pixel pairing per reference: pixel (h,w) uses w2[inds_r[n]],
// n = w*448 + h, but its OWN x_r row and OWN argmax in the final sum.
__global__ void __launch_bounds__(512)
k2_kernel(const float* __restrict__ w2, const float* __restrict__ b2,
          const float* __restrict__ w3, const float* __restrict__ b3,
          float* __restrict__ out)
{
    extern __shared__ float smem[];
    float* sxr    = smem;                    // [128 w][129] (c contiguous per pixel)
    int*   s_indr = (int*)(smem + 16512);    // 128
    int*   s_self = (int*)(smem + 16512 + 128);

    const int tid = threadIdx.x;
    const int wt = blockIdx.x, h = blockIdx.y;

    // conflict-free transpose load: lane owns pixel w, iterates channels
    for (int i = tid; i < 16384; i += 512) {
        int c = i >> 7, w = i & 127;
        sxr[w * 129 + c] = g_xr[(size_t)(h * 128 + c) * W_DIM + wt * 128 + w];
    }
    if (tid < 128) {
        int wg = wt * 128 + tid;
        int n = wg * H_DIM + h;                  // flattening order (w,h)
        s_indr[tid] = g_inds[n] + (n >> 9) * 128;
        s_self[tid] = g_inds[h * W_DIM + wg];
    }
    __syncthreads();

    const int warp = tid >> 5, lane = tid & 31;

    for (int i = 0; i < 8; i++) {
        const int wloc = warp * 8 + i;
        const int ind_r = s_indr[wloc];
        const float4* w2p = (const float4*)(w2 + (size_t)ind_r * 512);

        float ax = 0.f, ay = 0.f, az = 0.f, aw = 0.f;
#pragma unroll
        for (int j = 0; j < 4; j++) {
            float4 q = w2p[(j << 5) + lane];                 // coalesced 512B/warp
            float xv = sxr[wloc * 129 + (j << 5) + lane];    // conflict-free
            ax = fmaf(xv, q.x, ax);
            ay = fmaf(xv, q.y, ay);
            az = fmaf(xv, q.z, az);
            aw = fmaf(xv, q.w, aw);
        }
#pragma unroll
        for (int off = 16; off; off >>= 1) {
            ax += __shfl_xor_sync(0xffffffffu, ax, off);
            ay += __shfl_xor_sync(0xffffffffu, ay, off);
            az += __shfl_xor_sync(0xffffffffu, az, off);
            aw += __shfl_xor_sync(0xffffffffu, aw, off);
        }
        if (lane == 0) {
            float4 b2v = *(const float4*)&b2[ind_r * 4];
            float h0 = lrelu(ax + b2v.x);
            float h1 = lrelu(ay + b2v.y);
            float h2 = lrelu(az + b2v.z);
            float h3 = lrelu(aw + b2v.w);
            float4 w3v = *(const float4*)&w3[ind_r * 4];
            float r = fmaf(h0, w3v.x, fmaf(h1, w3v.y, fmaf(h2, w3v.z,
                      fmaf(h3, w3v.w, b3[ind_r]))));
            out[h * W_DIM + wt * 128 + wloc] =
                ((float)s_self[wloc] + r) * (1.0f / 128.0f);
        }
    }
}

extern "C" void kernel_launch(void* const* d_in, const int* in_sizes, int n_in,
                              void* d_out, int out_size)
{
    const float* x_in   = (const float*)d_in[0];
    const float* w_cl1  = (const float*)d_in[1];
    const float* b_cl1  = (const float*)d_in[2];
    const float* w_cl2  = (const float*)d_in[3];
    const float* b_cl2  = (const float*)d_in[4];
    const float* w_cl3  = (const float*)d_in[5];
    const float* b_cl3  = (const float*)d_in[6];
    const float* w_reg1 = (const float*)d_in[7];
    const float* b_reg1 = (const float*)d_in[8];
    const float* w2     = (const float*)d_in[9];
    const float* b2     = (const float*)d_in[10];
    const float* w3     = (const float*)d_in[11];
    const float* b3     = (const float*)d_in[12];
    float* out = (float*)d_out;

    const int smem2 = (16512 + 256) * 4;
    cudaFuncSetAttribute(k1_kernel, cudaFuncAttributeMaxDynamicSharedMemorySize, SMEM1_B);
    cudaFuncSetAttribute(k2_kernel, cudaFuncAttributeMaxDynamicSharedMemorySize, smem2);

    dim3 grid(4, H_DIM);
    k1_kernel<<<grid, 512, SMEM1_B>>>(x_in, w_cl1, b_cl1, w_cl2, b_cl2,
                                      w_cl3, b_cl3, w_reg1, b_reg1, out);
    k2_kernel<<<grid, 512, smem2>>>(w2, b2, w3, b3, out);
}

// round 14
// speedup vs baseline: 2.1439x; 1.8166x over previous
#include <cuda_runtime.h>
#include <cuda_fp16.h>
#include <cstdint>

#define H_DIM 448
#define W_DIM 512
#define HWTOT (448 * 512)

// Scratch (allocation-free rule: __device__ globals)
__device__ float g_xr[448 * 128 * 512];   // x_r in [h][c][w] layout
__device__ int   g_inds[448 * 512];       // argmax per pixel, (h,w) flat

__device__ __forceinline__ float lrelu(float v) { return v >= 0.0f ? v : 0.01f * v; }

// m16n8k16 fp16 mma, fp32 accumulate (sm_80 feature — compiles for compute_103)
__device__ __forceinline__ void mma16(float* d, uint4 a, uint2 b) {
    asm volatile(
        "mma.sync.aligned.m16n8k16.row.col.f32.f16.f16.f32 "
        "{%0,%1,%2,%3}, {%4,%5,%6,%7}, {%8,%9}, {%0,%1,%2,%3};"
        : "+f"(d[0]), "+f"(d[1]), "+f"(d[2]), "+f"(d[3])
        : "r"(a.x), "r"(a.y), "r"(a.z), "r"(a.w), "r"(b.x), "r"(b.y));
}

__device__ __forceinline__ uint32_t pack2(__half a, __half b) {
    return (uint32_t)__half_as_ushort(a) | ((uint32_t)__half_as_ushort(b) << 16);
}
// split (v0,v1) into fp16 hi + fp16 residual lo, packed as half2
__device__ __forceinline__ void split2(float v0, float v1, uint32_t& hi, uint32_t& lo) {
    __half h0 = __float2half_rn(v0);
    __half h1 = __float2half_rn(v1);
    __half e0 = __float2half_rn(v0 - __half2float(h0));
    __half e1 = __float2half_rn(v1 - __half2float(h1));
    hi = pack2(h0, h1);
    lo = pack2(e0, e1);
}

// ---------------- smem layout (bytes) ----------------
// A-frags: [8 ks][8 mt][32 lane] x uint4 per plane (32KB each)
// B-frags: [8 ks][16 nt][32 lane] x uint2 per plane (32KB each)
static constexpr int AFH_B   = 0;
static constexpr int AFL_B   = 32768;
static constexpr int BFH_B   = 65536;
static constexpr int BFL_B   = 98304;
static constexpr int XBUF_B  = 131072;   // 128x132 floats = 67584
static constexpr int SBIAS_B = 198656;   // 128 f
static constexpr int SMROW_B = 199168;   // 128 f
static constexpr int SMP_B   = 199680;   // 4x128 f
static constexpr int SAV_B   = 201728;   // 4x128 f
static constexpr int SAI_B   = 203776;   // 4x128 i
static constexpr int SMEM1_B = 205824;

// EPI: 0 = reg1 (x_r -> gmem), 1 = cl1 (split -> A), 2 = cl2 (split -> A + mask),
//      3 = cl3 (argmax, no activation)
template <int EPI>
__device__ void run_gemm(const float* __restrict__ Wg, const float* __restrict__ bias,
                         const float* __restrict__ mrow, const float* __restrict__ mbias,
                         char* sm, float* __restrict__ out, int wt, int h, int tid)
{
    uint4* AFH = (uint4*)(sm + AFH_B);
    uint4* AFL = (uint4*)(sm + AFL_B);
    uint2* BFH = (uint2*)(sm + BFH_B);
    uint2* BFL = (uint2*)(sm + BFL_B);
    float* sBias = (float*)(sm + SBIAS_B);
    float* sMrow = (float*)(sm + SMROW_B);
    float* sMP   = (float*)(sm + SMP_B);
    float* sAV   = (float*)(sm + SAV_B);
    int*   sAI   = (int*)(sm + SAI_B);

    const int warp = tid >> 5, lane = tid & 31;
    const int mi = warp >> 2, ni = warp & 3;
    const int g = lane >> 2, t = lane & 3;

    __syncthreads();   // prior epilogue A-writes visible; prior B-reads done

    if (tid < 128) sBias[tid] = bias[tid];
    if (EPI == 2 && tid < 128) sMrow[tid] = mrow[tid];

    // ---- stage whole B (128x128) into fragment slots, split hi/lo ----
#pragma unroll
    for (int k = 0; k < 8; k++) {
        int s = tid + 512 * k;
        int ls = s & 31, nt = (s >> 5) & 15, ks = s >> 9;
        int gs = ls >> 2, ts = ls & 3;
        int o = nt * 8 + gs, c0 = ks * 16 + 2 * ts;
        float2 w01 = *(const float2*)&Wg[o * 128 + c0];
        float2 w89 = *(const float2*)&Wg[o * 128 + c0 + 8];
        uint32_t bh0, bl0, bh1, bl1;
        split2(w01.x, w01.y, bh0, bl0);
        split2(w89.x, w89.y, bh1, bl1);
        BFH[s] = make_uint2(bh0, bh1);
        BFL[s] = make_uint2(bl0, bl1);
    }
    __syncthreads();

    float acc[2][4][4];
#pragma unroll
    for (int a = 0; a < 2; a++)
#pragma unroll
        for (int b = 0; b < 4; b++)
#pragma unroll
            for (int c = 0; c < 4; c++) acc[a][b][c] = 0.0f;

    // ---- mainloop: 8 k-steps, no syncs ----
#pragma unroll
    for (int ks = 0; ks < 8; ks++) {
        uint4 ah[2], al[2];
#pragma unroll
        for (int m2 = 0; m2 < 2; m2++) {
            int s = (ks * 8 + 2 * mi + m2) * 32 + lane;
            ah[m2] = AFH[s];
            al[m2] = AFL[s];
        }
        uint2 bh[4], bl[4];
#pragma unroll
        for (int n4 = 0; n4 < 4; n4++) {
            int s = (ks * 16 + ni * 4 + n4) * 32 + lane;
            bh[n4] = BFH[s];
            bl[n4] = BFL[s];
        }
#pragma unroll
        for (int m2 = 0; m2 < 2; m2++)
#pragma unroll
            for (int n4 = 0; n4 < 4; n4++) {
                float* d = acc[m2][n4];
                mma16(d, al[m2], bh[n4]);   // lo x hi
                mma16(d, ah[m2], bl[n4]);   // hi x lo
                mma16(d, ah[m2], bh[n4]);   // hi x hi (largest last)
            }
    }

    // ---------------- epilogue from D fragments ----------------
    // d[j]: R = (2mi+m2)*16 + g + 8*(j>>1), C = (ni*4+n4)*8 + 2t + (j&1)
    if (EPI == 0) {
#pragma unroll
        for (int m2 = 0; m2 < 2; m2++)
#pragma unroll
            for (int n4 = 0; n4 < 4; n4++)
#pragma unroll
                for (int j = 0; j < 4; j++) {
                    int C = (ni * 4 + n4) * 8 + 2 * t + (j & 1);
                    int R = (2 * mi + m2) * 16 + g + 8 * (j >> 1);
                    float v = lrelu(acc[m2][n4][j] + sBias[C]);
                    g_xr[(size_t)(h * 128 + C) * W_DIM + wt * 128 + R] = v;
                }
    } else if (EPI == 1 || EPI == 2) {
        __syncthreads();   // all mainloop A-reads done before overwrite
        float mp[2][2] = {{0.f, 0.f}, {0.f, 0.f}};
#pragma unroll
        for (int m2 = 0; m2 < 2; m2++) {
#pragma unroll
            for (int q = 0; q < 2; q++) {
                float v[2][4];
#pragma unroll
                for (int e = 0; e < 2; e++) {
                    int n4 = 2 * q + e;
#pragma unroll
                    for (int j = 0; j < 4; j++) {
                        int C = (ni * 4 + n4) * 8 + 2 * t + (j & 1);
                        float vv = lrelu(acc[m2][n4][j] + sBias[C]);
                        v[e][j] = vv;
                        if (EPI == 2) mp[m2][j >> 1] = fmaf(vv, sMrow[C], mp[m2][j >> 1]);
                    }
                }
                // thread's own (m2, n4=2q,2q+1) accs form exactly A-slot
                // (ks = 2ni+q, mt = 2mi+m2) at its OWN lane -> conflict-free
                uint32_t h0, l0, h1, l1, h2, l2, h3, l3;
                split2(v[0][0], v[0][1], h0, l0);
                split2(v[0][2], v[0][3], h1, l1);
                split2(v[1][0], v[1][1], h2, l2);
                split2(v[1][2], v[1][3], h3, l3);
                int slot = ((2 * ni + q) * 8 + 2 * mi + m2) * 32 + lane;
                AFH[slot] = make_uint4(h0, h1, h2, h3);
                AFL[slot] = make_uint4(l0, l1, l2, l3);
            }
        }
        if (EPI == 2) {
#pragma unroll
            for (int m2 = 0; m2 < 2; m2++)
#pragma unroll
                for (int rh = 0; rh < 2; rh++) {
                    mp[m2][rh] += __shfl_xor_sync(0xffffffffu, mp[m2][rh], 1);
                    mp[m2][rh] += __shfl_xor_sync(0xffffffffu, mp[m2][rh], 2);
                }
            if (t == 0) {
#pragma unroll
                for (int m2 = 0; m2 < 2; m2++)
#pragma unroll
                    for (int rh = 0; rh < 2; rh++) {
                        int R = (2 * mi + m2) * 16 + g + 8 * rh;
                        sMP[ni * 128 + R] = mp[m2][rh];
                    }
            }
            __syncthreads();
            if (tid < 128) {
                float m = sMP[tid] + sMP[128 + tid] + sMP[256 + tid] + sMP[384 + tid]
                        + __ldg(mbias);
                out[HWTOT + h * W_DIM + wt * 128 + tid] = lrelu(m);
            }
        }
    } else {  // EPI == 3: argmax (first-max-on-tie like jnp.argmax)
#pragma unroll
        for (int m2 = 0; m2 < 2; m2++)
#pragma unroll
            for (int rh = 0; rh < 2; rh++) {
                float bv = -3.4e38f; int bi = 0;
#pragma unroll
                for (int n4 = 0; n4 < 4; n4++)
#pragma unroll
                    for (int jb = 0; jb < 2; jb++) {
                        int C = (ni * 4 + n4) * 8 + 2 * t + jb;
                        float v = acc[m2][n4][rh * 2 + jb] + sBias[C];
                        if (v > bv) { bv = v; bi = C; }
                    }
#pragma unroll
                for (int off = 1; off <= 2; off <<= 1) {
                    float ov = __shfl_xor_sync(0xffffffffu, bv, off);
                    int   oi = __shfl_xor_sync(0xffffffffu, bi, off);
                    if (ov > bv || (ov == bv && oi < bi)) { bv = ov; bi = oi; }
                }
                if (t == 0) {
                    int R = (2 * mi + m2) * 16 + g + 8 * rh;
                    sAV[ni * 128 + R] = bv;
                    sAI[ni * 128 + R] = bi;
                }
            }
        __syncthreads();
        if (tid < 128) {
            float b = sAV[tid]; int x = sAI[tid];
#pragma unroll
            for (int q = 1; q < 4; q++) {
                float ov = sAV[q * 128 + tid];
                int   oi = sAI[q * 128 + tid];
                if (ov > b || (ov == b && oi < x)) { b = ov; x = oi; }
            }
            g_inds[h * W_DIM + wt * 128 + tid] = x;
        }
    }
}

// K1: per (wtile, h): x -> A-frags, then reg1, cl1, cl2(+mask), cl3(+argmax)
__global__ void __launch_bounds__(512, 1)
k1_kernel(const float* __restrict__ x_in,
          const float* __restrict__ w_cl1, const float* __restrict__ b_cl1,
          const float* __restrict__ w_cl2, const float* __restrict__ b_cl2,
          const float* __restrict__ w_cl3, const float* __restrict__ b_cl3,
          const float* __restrict__ w_reg1, const float* __restrict__ b_reg1,
          float* __restrict__ out)
{
    extern __shared__ char sm[];
    float* xbuf = (float*)(sm + XBUF_B);
    uint4* AFH = (uint4*)(sm + AFH_B);
    uint4* AFL = (uint4*)(sm + AFL_B);
    const int tid = threadIdx.x;
    const int wt = blockIdx.x, h = blockIdx.y;

    // coalesced x load into bounce buffer [c][w]
    const float* xsrc = x_in + (size_t)h * W_DIM + wt * 128;
    for (int i = tid; i < 4096; i += 512) {
        int c = i >> 5, w4 = (i & 31) << 2;
        *(float4*)&xbuf[c * 132 + w4] = *(const float4*)&xsrc[(size_t)c * HWTOT + w4];
    }
    __syncthreads();

    // restage into A-fragment slots (thread builds whole uint4 slots: both
    // reads and STS.128 writes conflict-free)
#pragma unroll
    for (int k = 0; k < 4; k++) {
        int s = tid + 512 * k;
        int ls = s & 31, mt = (s >> 5) & 7, ks = s >> 8;
        int gs = ls >> 2, ts = ls & 3;
        int R0 = mt * 16 + gs, C0 = ks * 16 + 2 * ts;
        float v00 = xbuf[(C0 + 0) * 132 + R0],     v01 = xbuf[(C0 + 1) * 132 + R0];
        float v10 = xbuf[(C0 + 0) * 132 + R0 + 8], v11 = xbuf[(C0 + 1) * 132 + R0 + 8];
        float v02 = xbuf[(C0 + 8) * 132 + R0],     v03 = xbuf[(C0 + 9) * 132 + R0];
        float v12 = xbuf[(C0 + 8) * 132 + R0 + 8], v13 = xbuf[(C0 + 9) * 132 + R0 + 8];
        uint32_t h0, l0, h1, l1, h2, l2, h3, l3;
        split2(v00, v01, h0, l0);
        split2(v10, v11, h1, l1);
        split2(v02, v03, h2, l2);
        split2(v12, v13, h3, l3);
        AFH[s] = make_uint4(h0, h1, h2, h3);
        AFL[s] = make_uint4(l0, l1, l2, l3);
    }

    run_gemm<0>(w_reg1 + h * 16384, b_reg1 + h * 128, nullptr, nullptr,
                sm, out, wt, h, tid);
    run_gemm<1>(w_cl1 + h * 16384, b_cl1 + h * 128, nullptr, nullptr,
                sm, out, wt, h, tid);
    run_gemm<2>(w_cl2 + h * 16384, b_cl2 + h * 128,
                w_cl3 + h * 16512 + 16384, b_cl3 + h * 129 + 128,
                sm, out, wt, h, tid);
    run_gemm<3>(w_cl3 + h * 16512, b_cl3 + h * 129, nullptr, nullptr,
                sm, out, wt, h, tid);
}

// K2: gathered regressor head + final output. One warp per pixel, 512 threads.
// Cross-pixel pairing per reference: pixel (h,w) uses w2[inds_r[n]],
// n = w*448 + h, but its OWN x_r row and OWN argmax in the final sum.
__global__ void __launch_bounds__(512)
k2_kernel(const float* __restrict__ w2, const float* __restrict__ b2,
          const float* __restrict__ w3, const float* __restrict__ b3,
          float* __restrict__ out)
{
    extern __shared__ float smem[];
    float* sxr    = smem;                    // [128 w][129] (c contiguous per pixel)
    int*   s_indr = (int*)(smem + 16512);    // 128
    int*   s_self = (int*)(smem + 16512 + 128);

    const int tid = threadIdx.x;
    const int wt = blockIdx.x, h = blockIdx.y;

    // conflict-free transpose load: lane owns pixel w, iterates channels
    for (int i = tid; i < 16384; i += 512) {
        int c = i >> 7, w = i & 127;
        sxr[w * 129 + c] = g_xr[(size_t)(h * 128 + c) * W_DIM + wt * 128 + w];
    }
    if (tid < 128) {
        int wg = wt * 128 + tid;
        int n = wg * H_DIM + h;                  // flattening order (w,h)
        s_indr[tid] = g_inds[n] + (n >> 9) * 128;
        s_self[tid] = g_inds[h * W_DIM + wg];
    }
    __syncthreads();

    const int warp = tid >> 5, lane = tid & 31;

    for (int i = 0; i < 8; i++) {
        const int wloc = warp * 8 + i;
        const int ind_r = s_indr[wloc];
        const float4* w2p = (const float4*)(w2 + (size_t)ind_r * 512);

        float ax = 0.f, ay = 0.f, az = 0.f, aw = 0.f;
#pragma unroll
        for (int j = 0; j < 4; j++) {
            float4 q = w2p[(j << 5) + lane];                 // coalesced 512B/warp
            float xv = sxr[wloc * 129 + (j << 5) + lane];    // conflict-free
            ax = fmaf(xv, q.x, ax);
            ay = fmaf(xv, q.y, ay);
            az = fmaf(xv, q.z, az);
            aw = fmaf(xv, q.w, aw);
        }
#pragma unroll
        for (int off = 16; off; off >>= 1) {
            ax += __shfl_xor_sync(0xffffffffu, ax, off);
            ay += __shfl_xor_sync(0xffffffffu, ay, off);
            az += __shfl_xor_sync(0xffffffffu, az, off);
            aw += __shfl_xor_sync(0xffffffffu, aw, off);
        }
        if (lane == 0) {
            float4 b2v = *(const float4*)&b2[ind_r * 4];
            float h0 = lrelu(ax + b2v.x);
            float h1 = lrelu(ay + b2v.y);
            float h2 = lrelu(az + b2v.z);
            float h3 = lrelu(aw + b2v.w);
            float4 w3v = *(const float4*)&w3[ind_r * 4];
            float r = fmaf(h0, w3v.x, fmaf(h1, w3v.y, fmaf(h2, w3v.z,
                      fmaf(h3, w3v.w, b3[ind_r]))));
            out[h * W_DIM + wt * 128 + wloc] =
                ((float)s_self[wloc] + r) * (1.0f / 128.0f);
        }
    }
}

// empty dummies to shift ncu's "-s 5" capture onto k1 (launch order per call:
// dummy, k1, k2, dummy -> global launch index 5 = replay #1's k1)
__global__ void dummy_kernel() {}

extern "C" void kernel_launch(void* const* d_in, const int* in_sizes, int n_in,
                              void* d_out, int out_size)
{
    const float* x_in   = (const float*)d_in[0];
    const float* w_cl1  = (const float*)d_in[1];
    const float* b_cl1  = (const float*)d_in[2];
    const float* w_cl2  = (const float*)d_in[3];
    const float* b_cl2  = (const float*)d_in[4];
    const float* w_cl3  = (const float*)d_in[5];
    const float* b_cl3  = (const float*)d_in[6];
    const float* w_reg1 = (const float*)d_in[7];
    const float* b_reg1 = (const float*)d_in[8];
    const float* w2     = (const float*)d_in[9];
    const float* b2     = (const float*)d_in[10];
    const float* w3     = (const float*)d_in[11];
    const float* b3     = (const float*)d_in[12];
    float* out = (float*)d_out;

    const int smem2 = (16512 + 256) * 4;
    cudaFuncSetAttribute(k1_kernel, cudaFuncAttributeMaxDynamicSharedMemorySize, SMEM1_B);
    cudaFuncSetAttribute(k2_kernel, cudaFuncAttributeMaxDynamicSharedMemorySize, smem2);

    dim3 grid(4, H_DIM);
    dummy_kernel<<<1, 32>>>();
    k1_kernel<<<grid, 512, SMEM1_B>>>(x_in, w_cl1, b_cl1, w_cl2, b_cl2,
                                      w_cl3, b_cl3, w_reg1, b_reg1, out);
    k2_kernel<<<grid, 512, smem2>>>(w2, b2, w3, b3, out);
    dummy_kernel<<<1, 32>>>();
}

// round 15
// speedup vs baseline: 2.2012x; 1.0267x over previous
#include <cuda_runtime.h>
#include <cuda_fp16.h>
#include <cstdint>

#define H_DIM 448
#define W_DIM 512
#define HWTOT (448 * 512)

// Scratch (allocation-free rule: __device__ globals)
__device__ float g_xr[448 * 128 * 512];   // x_r in [h][c][w] layout
__device__ int   g_inds[448 * 512];       // argmax per pixel, (h,w) flat

__device__ __forceinline__ float lrelu(float v) { return v >= 0.0f ? v : 0.01f * v; }

// m16n8k16 fp16 mma, fp32 accumulate (sm_80 feature — compiles for compute_103)
__device__ __forceinline__ void mma16(float* d, uint4 a, uint2 b) {
    asm volatile(
        "mma.sync.aligned.m16n8k16.row.col.f32.f16.f16.f32 "
        "{%0,%1,%2,%3}, {%4,%5,%6,%7}, {%8,%9}, {%0,%1,%2,%3};"
        : "+f"(d[0]), "+f"(d[1]), "+f"(d[2]), "+f"(d[3])
        : "r"(a.x), "r"(a.y), "r"(a.z), "r"(a.w), "r"(b.x), "r"(b.y));
}

// split (v0,v1) into fp16 hi + fp16 residual lo, packed as half2.
// Uses cvt.rn.f16x2.f32 (1 instr per packed pair).
__device__ __forceinline__ void split2(float v0, float v1, uint32_t& hi, uint32_t& lo) {
    __half2 h = __float22half2_rn(make_float2(v0, v1));
    float2 hf = __half22float2(h);
    __half2 e = __float22half2_rn(make_float2(v0 - hf.x, v1 - hf.y));
    hi = *(uint32_t*)&h;
    lo = *(uint32_t*)&e;
}

// ---------------- smem layout (bytes) ----------------
// A-frags: [8 ks][8 mt][32 lane] x uint4 per plane (32KB each)
// B-frags: [8 ks][16 nt][32 lane] x uint2 per plane (32KB each)
static constexpr int AFH_B   = 0;
static constexpr int AFL_B   = 32768;
static constexpr int BFH_B   = 65536;
static constexpr int BFL_B   = 98304;
static constexpr int XBUF_B  = 131072;   // 128x132 floats = 67584
static constexpr int SBIAS_B = 198656;   // 128 f
static constexpr int SMROW_B = 199168;   // 128 f
static constexpr int SMP_B   = 199680;   // 4x128 f
static constexpr int SAV_B   = 201728;   // 4x128 f
static constexpr int SAI_B   = 203776;   // 4x128 i
static constexpr int SMEM1_B = 205824;

// EPI: 0 = reg1 (x_r -> gmem via smem bounce), 1 = cl1 (split -> A),
//      2 = cl2 (split -> A + mask), 3 = cl3 (argmax, no activation)
template <int EPI>
__device__ void run_gemm(const float* __restrict__ Wg, const float* __restrict__ bias,
                         const float* __restrict__ mrow, const float* __restrict__ mbias,
                         char* sm, float* __restrict__ out, int wt, int h, int tid)
{
    uint4* AFH = (uint4*)(sm + AFH_B);
    uint4* AFL = (uint4*)(sm + AFL_B);
    uint2* BFH = (uint2*)(sm + BFH_B);
    uint2* BFL = (uint2*)(sm + BFL_B);
    float* xbuf  = (float*)(sm + XBUF_B);
    float* sBias = (float*)(sm + SBIAS_B);
    float* sMrow = (float*)(sm + SMROW_B);
    float* sMP   = (float*)(sm + SMP_B);
    float* sAV   = (float*)(sm + SAV_B);
    int*   sAI   = (int*)(sm + SAI_B);

    const int warp = tid >> 5, lane = tid & 31;
    const int mi = warp >> 2, ni = warp & 3;
    const int g = lane >> 2, t = lane & 3;

    // ---- hoisted B loads: pure gmem reads, issue BEFORE the entry barrier so
    // their latency overlaps the prior epilogue's drain ----
    float2 wraw[8][2];
    int ls = tid & 31, ntv = (tid >> 5) & 15;
    int gs = ls >> 2, ts = ls & 3;
    int o = ntv * 8 + gs;
#pragma unroll
    for (int k = 0; k < 8; k++) {
        int ks = k;   // s = tid + 512k -> ks = s>>9 iterates 0..7 for fixed tid
        int c0 = ks * 16 + 2 * ts;
        wraw[k][0] = *(const float2*)&Wg[o * 128 + c0];
        wraw[k][1] = *(const float2*)&Wg[o * 128 + c0 + 8];
    }

    __syncthreads();   // prior epilogue A-writes visible; prior B-reads done

    if (tid < 128) sBias[tid] = bias[tid];
    if (EPI == 2 && tid < 128) sMrow[tid] = mrow[tid];

    // ---- stage B into fragment slots, split hi/lo ----
#pragma unroll
    for (int k = 0; k < 8; k++) {
        int s = (k * 16 + ntv) * 32 + ls;    // [ks][nt][lane]
        uint32_t bh0, bl0, bh1, bl1;
        split2(wraw[k][0].x, wraw[k][0].y, bh0, bl0);
        split2(wraw[k][1].x, wraw[k][1].y, bh1, bl1);
        BFH[s] = make_uint2(bh0, bh1);
        BFL[s] = make_uint2(bl0, bl1);
    }
    __syncthreads();

    float acc[2][4][4];
#pragma unroll
    for (int a = 0; a < 2; a++)
#pragma unroll
        for (int b = 0; b < 4; b++)
#pragma unroll
            for (int c = 0; c < 4; c++) acc[a][b][c] = 0.0f;

    // ---- mainloop: 8 k-steps, no syncs ----
#pragma unroll
    for (int ks = 0; ks < 8; ks++) {
        uint4 ah[2], al[2];
#pragma unroll
        for (int m2 = 0; m2 < 2; m2++) {
            int s = (ks * 8 + 2 * mi + m2) * 32 + lane;
            ah[m2] = AFH[s];
            al[m2] = AFL[s];
        }
        uint2 bh[4], bl[4];
#pragma unroll
        for (int n4 = 0; n4 < 4; n4++) {
            int s = (ks * 16 + ni * 4 + n4) * 32 + lane;
            bh[n4] = BFH[s];
            bl[n4] = BFL[s];
        }
#pragma unroll
        for (int m2 = 0; m2 < 2; m2++)
#pragma unroll
            for (int n4 = 0; n4 < 4; n4++) {
                float* d = acc[m2][n4];
                mma16(d, al[m2], bh[n4]);   // lo x hi
                mma16(d, ah[m2], bl[n4]);   // hi x lo
                mma16(d, ah[m2], bh[n4]);   // hi x hi (largest last)
            }
    }

    // ---------------- epilogue from D fragments ----------------
    // d[j]: R = (2mi+m2)*16 + g + 8*(j>>1), C = (ni*4+n4)*8 + 2t + (j&1)
    if (EPI == 0) {
        // scatter to xbuf[C][132+R]; bank = (8t+g) mod 32 -> conflict-free
#pragma unroll
        for (int m2 = 0; m2 < 2; m2++)
#pragma unroll
            for (int n4 = 0; n4 < 4; n4++)
#pragma unroll
                for (int j = 0; j < 4; j++) {
                    int C = (ni * 4 + n4) * 8 + 2 * t + (j & 1);
                    int R = (2 * mi + m2) * 16 + g + 8 * (j >> 1);
                    xbuf[C * 132 + R] = lrelu(acc[m2][n4][j] + sBias[C]);
                }
        __syncthreads();
        for (int i = tid; i < 4096; i += 512) {
            int c = i >> 5, w4 = (i & 31) << 2;
            *(float4*)&g_xr[(size_t)(h * 128 + c) * W_DIM + wt * 128 + w4] =
                *(float4*)&xbuf[c * 132 + w4];
        }
    } else if (EPI == 1 || EPI == 2) {
        __syncthreads();   // all mainloop A-reads done before overwrite
        float mp[2][2] = {{0.f, 0.f}, {0.f, 0.f}};
#pragma unroll
        for (int m2 = 0; m2 < 2; m2++) {
#pragma unroll
            for (int q = 0; q < 2; q++) {
                float v[2][4];
#pragma unroll
                for (int e = 0; e < 2; e++) {
                    int n4 = 2 * q + e;
#pragma unroll
                    for (int j = 0; j < 4; j++) {
                        int C = (ni * 4 + n4) * 8 + 2 * t + (j & 1);
                        float vv = lrelu(acc[m2][n4][j] + sBias[C]);
                        v[e][j] = vv;
                        if (EPI == 2) mp[m2][j >> 1] = fmaf(vv, sMrow[C], mp[m2][j >> 1]);
                    }
                }
                // thread's own (m2, n4=2q,2q+1) accs form exactly A-slot
                // (ks = 2ni+q, mt = 2mi+m2) at its OWN lane -> conflict-free
                uint32_t h0, l0, h1, l1, h2, l2, h3, l3;
                split2(v[0][0], v[0][1], h0, l0);
                split2(v[0][2], v[0][3], h1, l1);
                split2(v[1][0], v[1][1], h2, l2);
                split2(v[1][2], v[1][3], h3, l3);
                int slot = ((2 * ni + q) * 8 + 2 * mi + m2) * 32 + lane;
                AFH[slot] = make_uint4(h0, h1, h2, h3);
                AFL[slot] = make_uint4(l0, l1, l2, l3);
            }
        }
        if (EPI == 2) {
#pragma unroll
            for (int m2 = 0; m2 < 2; m2++)
#pragma unroll
                for (int rh = 0; rh < 2; rh++) {
                    mp[m2][rh] += __shfl_xor_sync(0xffffffffu, mp[m2][rh], 1);
                    mp[m2][rh] += __shfl_xor_sync(0xffffffffu, mp[m2][rh], 2);
                }
            if (t == 0) {
#pragma unroll
                for (int m2 = 0; m2 < 2; m2++)
#pragma unroll
                    for (int rh = 0; rh < 2; rh++) {
                        int R = (2 * mi + m2) * 16 + g + 8 * rh;
                        sMP[ni * 128 + R] = mp[m2][rh];
                    }
            }
            __syncthreads();
            if (tid < 128) {
                float m = sMP[tid] + sMP[128 + tid] + sMP[256 + tid] + sMP[384 + tid]
                        + __ldg(mbias);
                out[HWTOT + h * W_DIM + wt * 128 + tid] = lrelu(m);
            }
        }
    } else {  // EPI == 3: argmax (first-max-on-tie like jnp.argmax)
#pragma unroll
        for (int m2 = 0; m2 < 2; m2++)
#pragma unroll
            for (int rh = 0; rh < 2; rh++) {
                float bv = -3.4e38f; int bi = 0;
#pragma unroll
                for (int n4 = 0; n4 < 4; n4++)
#pragma unroll
                    for (int jb = 0; jb < 2; jb++) {
                        int C = (ni * 4 + n4) * 8 + 2 * t + jb;
                        float v = acc[m2][n4][rh * 2 + jb] + sBias[C];
                        if (v > bv) { bv = v; bi = C; }
                    }
#pragma unroll
                for (int off = 1; off <= 2; off <<= 1) {
                    float ov = __shfl_xor_sync(0xffffffffu, bv, off);
                    int   oi = __shfl_xor_sync(0xffffffffu, bi, off);
                    if (ov > bv || (ov == bv && oi < bi)) { bv = ov; bi = oi; }
                }
                if (t == 0) {
                    int R = (2 * mi + m2) * 16 + g + 8 * rh;
                    sAV[ni * 128 + R] = bv;
                    sAI[ni * 128 + R] = bi;
                }
            }
        __syncthreads();
        if (tid < 128) {
            float b = sAV[tid]; int x = sAI[tid];
#pragma unroll
            for (int q = 1; q < 4; q++) {
                float ov = sAV[q * 128 + tid];
                int   oi = sAI[q * 128 + tid];
                if (ov > b || (ov == b && oi < x)) { b = ov; x = oi; }
            }
            g_inds[h * W_DIM + wt * 128 + tid] = x;
        }
    }
}

// K1: per (wtile, h): x -> A-frags, then reg1, cl1, cl2(+mask), cl3(+argmax)
__global__ void __launch_bounds__(512, 1)
k1_kernel(const float* __restrict__ x_in,
          const float* __restrict__ w_cl1, const float* __restrict__ b_cl1,
          const float* __restrict__ w_cl2, const float* __restrict__ b_cl2,
          const float* __restrict__ w_cl3, const float* __restrict__ b_cl3,
          const float* __restrict__ w_reg1, const float* __restrict__ b_reg1,
          float* __restrict__ out)
{
    extern __shared__ char sm[];
    float* xbuf = (float*)(sm + XBUF_B);
    uint4* AFH = (uint4*)(sm + AFH_B);
    uint4* AFL = (uint4*)(sm + AFL_B);
    const int tid = threadIdx.x;
    const int wt = blockIdx.x, h = blockIdx.y;

    // coalesced x load into bounce buffer [c][w]
    const float* xsrc = x_in + (size_t)h * W_DIM + wt * 128;
    for (int i = tid; i < 4096; i += 512) {
        int c = i >> 5, w4 = (i & 31) << 2;
        *(float4*)&xbuf[c * 132 + w4] = *(const float4*)&xsrc[(size_t)c * HWTOT + w4];
    }
    __syncthreads();

    // restage into A-fragment slots (thread builds whole uint4 slots: both
    // reads and STS.128 writes conflict-free)
#pragma unroll
    for (int k = 0; k < 4; k++) {
        int s = tid + 512 * k;
        int ls = s & 31, mt = (s >> 5) & 7, ks = s >> 8;
        int gs = ls >> 2, ts = ls & 3;
        int R0 = mt * 16 + gs, C0 = ks * 16 + 2 * ts;
        float v00 = xbuf[(C0 + 0) * 132 + R0],     v01 = xbuf[(C0 + 1) * 132 + R0];
        float v10 = xbuf[(C0 + 0) * 132 + R0 + 8], v11 = xbuf[(C0 + 1) * 132 + R0 + 8];
        float v02 = xbuf[(C0 + 8) * 132 + R0],     v03 = xbuf[(C0 + 9) * 132 + R0];
        float v12 = xbuf[(C0 + 8) * 132 + R0 + 8], v13 = xbuf[(C0 + 9) * 132 + R0 + 8];
        uint32_t h0, l0, h1, l1, h2, l2, h3, l3;
        split2(v00, v01, h0, l0);
        split2(v10, v11, h1, l1);
        split2(v02, v03, h2, l2);
        split2(v12, v13, h3, l3);
        AFH[s] = make_uint4(h0, h1, h2, h3);
        AFL[s] = make_uint4(l0, l1, l2, l3);
    }

    run_gemm<0>(w_reg1 + h * 16384, b_reg1 + h * 128, nullptr, nullptr,
                sm, out, wt, h, tid);
    run_gemm<1>(w_cl1 + h * 16384, b_cl1 + h * 128, nullptr, nullptr,
                sm, out, wt, h, tid);
    run_gemm<2>(w_cl2 + h * 16384, b_cl2 + h * 128,
                w_cl3 + h * 16512 + 16384, b_cl3 + h * 129 + 128,
                sm, out, wt, h, tid);
    run_gemm<3>(w_cl3 + h * 16512, b_cl3 + h * 129, nullptr, nullptr,
                sm, out, wt, h, tid);
}

// K2: gathered regressor head + final output. One warp per pixel, 512 threads.
// Cross-pixel pairing per reference: pixel (h,w) uses w2[inds_r[n]],
// n = w*448 + h, but its OWN x_r row and OWN argmax in the final sum.
__global__ void __launch_bounds__(512)
k2_kernel(const float* __restrict__ w2, const float* __restrict__ b2,
          const float* __restrict__ w3, const float* __restrict__ b3,
          float* __restrict__ out)
{
    extern __shared__ float smem[];
    float* sxr    = smem;                    // [128 w][129] (c contiguous per pixel)
    int*   s_indr = (int*)(smem + 16512);    // 128
    int*   s_self = (int*)(smem + 16512 + 128);

    const int tid = threadIdx.x;
    const int wt = blockIdx.x, h = blockIdx.y;

    // conflict-free transpose load: lane owns pixel w, iterates channels
    for (int i = tid; i < 16384; i += 512) {
        int c = i >> 7, w = i & 127;
        sxr[w * 129 + c] = g_xr[(size_t)(h * 128 + c) * W_DIM + wt * 128 + w];
    }
    if (tid < 128) {
        int wg = wt * 128 + tid;
        int n = wg * H_DIM + h;                  // flattening order (w,h)
        s_indr[tid] = g_inds[n] + (n >> 9) * 128;
        s_self[tid] = g_inds[h * W_DIM + wg];
    }
    __syncthreads();

    const int warp = tid >> 5, lane = tid & 31;

    for (int i = 0; i < 8; i++) {
        const int wloc = warp * 8 + i;
        const int ind_r = s_indr[wloc];
        const float4* w2p = (const float4*)(w2 + (size_t)ind_r * 512);

        float ax = 0.f, ay = 0.f, az = 0.f, aw = 0.f;
#pragma unroll
        for (int j = 0; j < 4; j++) {
            float4 q = w2p[(j << 5) + lane];                 // coalesced 512B/warp
            float xv = sxr[wloc * 129 + (j << 5) + lane];    // conflict-free
            ax = fmaf(xv, q.x, ax);
            ay = fmaf(xv, q.y, ay);
            az = fmaf(xv, q.z, az);
            aw = fmaf(xv, q.w, aw);
        }
#pragma unroll
        for (int off = 16; off; off >>= 1) {
            ax += __shfl_xor_sync(0xffffffffu, ax, off);
            ay += __shfl_xor_sync(0xffffffffu, ay, off);
            az += __shfl_xor_sync(0xffffffffu, az, off);
            aw += __shfl_xor_sync(0xffffffffu, aw, off);
        }
        if (lane == 0) {
            float4 b2v = *(const float4*)&b2[ind_r * 4];
            float h0 = lrelu(ax + b2v.x);
            float h1 = lrelu(ay + b2v.y);
            float h2 = lrelu(az + b2v.z);
            float h3 = lrelu(aw + b2v.w);
            float4 w3v = *(const float4*)&w3[ind_r * 4];
            float r = fmaf(h0, w3v.x, fmaf(h1, w3v.y, fmaf(h2, w3v.z,
                      fmaf(h3, w3v.w, b3[ind_r]))));
            out[h * W_DIM + wt * 128 + wloc] =
                ((float)s_self[wloc] + r) * (1.0f / 128.0f);
        }
    }
}

// dummies AFTER the real kernels: sequence length 4 -> correctness call =
// launches 1..4, so ncu's "-s 5 -c 1" lands on replay-1's k1_kernel.
__global__ void dummy_kernel() {}

extern "C" void kernel_launch(void* const* d_in, const int* in_sizes, int n_in,
                              void* d_out, int out_size)
{
    const float* x_in   = (const float*)d_in[0];
    const float* w_cl1  = (const float*)d_in[1];
    const float* b_cl1  = (const float*)d_in[2];
    const float* w_cl2  = (const float*)d_in[3];
    const float* b_cl2  = (const float*)d_in[4];
    const float* w_cl3  = (const float*)d_in[5];
    const float* b_cl3  = (const float*)d_in[6];
    const float* w_reg1 = (const float*)d_in[7];
    const float* b_reg1 = (const float*)d_in[8];
    const float* w2     = (const float*)d_in[9];
    const float* b2     = (const float*)d_in[10];
    const float* w3     = (const float*)d_in[11];
    const float* b3     = (const float*)d_in[12];
    float* out = (float*)d_out;

    const int smem2 = (16512 + 256) * 4;
    cudaFuncSetAttribute(k1_kernel, cudaFuncAttributeMaxDynamicSharedMemorySize, SMEM1_B);
    cudaFuncSetAttribute(k2_kernel, cudaFuncAttributeMaxDynamicSharedMemorySize, smem2);

    dim3 grid(4, H_DIM);
    k1_kernel<<<grid, 512, SMEM1_B>>>(x_in, w_cl1, b_cl1, w_cl2, b_cl2,
                                      w_cl3, b_cl3, w_reg1, b_reg1, out);
    k2_kernel<<<grid, 512, smem2>>>(w2, b2, w3, b3, out);
    dummy_kernel<<<1, 32>>>();
    dummy_kernel<<<1, 32>>>();
}

// round 16
// speedup vs baseline: 2.2640x; 1.0285x over previous
#include <cuda_runtime.h>
#include <cuda_fp16.h>
#include <cstdint>

#define H_DIM 448
#define W_DIM 512
#define HWTOT (448 * 512)

// Scratch (allocation-free rule: __device__ globals)
__device__ float g_xr[448 * 128 * 512];   // x_r in [h][c][w] layout
__device__ int   g_inds[448 * 512];       // argmax per pixel, (h,w) flat

__device__ __forceinline__ float lrelu(float v) { return v >= 0.0f ? v : 0.01f * v; }

// m16n8k16 fp16 mma, fp32 accumulate (sm_80 feature — compiles for compute_103)
__device__ __forceinline__ void mma16(float* d, uint4 a, uint2 b) {
    asm volatile(
        "mma.sync.aligned.m16n8k16.row.col.f32.f16.f16.f32 "
        "{%0,%1,%2,%3}, {%4,%5,%6,%7}, {%8,%9}, {%0,%1,%2,%3};"
        : "+f"(d[0]), "+f"(d[1]), "+f"(d[2]), "+f"(d[3])
        : "r"(a.x), "r"(a.y), "r"(a.z), "r"(a.w), "r"(b.x), "r"(b.y));
}

// split (v0,v1) into fp16 hi + fp16 residual lo, packed as half2.
__device__ __forceinline__ void split2(float v0, float v1, uint32_t& hi, uint32_t& lo) {
    __half2 h = __float22half2_rn(make_float2(v0, v1));
    float2 hf = __half22float2(h);
    __half2 e = __float22half2_rn(make_float2(v0 - hf.x, v1 - hf.y));
    hi = *(uint32_t*)&h;
    lo = *(uint32_t*)&e;
}

// ---------------- smem layout (bytes) ----------------
// A-frags: [8 ks][8 mt][32 lane] x uint4 per plane (32KB each)
// B-frags: [8 ks][16 nt][32 lane] x uint2 per plane (32KB each)
static constexpr int AFH_B   = 0;
static constexpr int AFL_B   = 32768;
static constexpr int BFH_B   = 65536;
static constexpr int BFL_B   = 98304;
static constexpr int XBUF_B  = 131072;   // 128x132 floats = 67584
static constexpr int SBIAS_B = 198656;   // 128 f
static constexpr int SMROW_B = 199168;   // 128 f
static constexpr int SMP_B   = 199680;   // 4x128 f
static constexpr int SAV_B   = 201728;   // 4x128 f
static constexpr int SAI_B   = 203776;   // 4x128 i
static constexpr int SMEM1_B = 205824;

// EPI: 0 = reg1 (2-term split, x_r -> gmem via smem bounce), 1 = cl1 (split -> A),
//      2 = cl2 (split -> A + mask), 3 = cl3 (argmax, no activation)
template <int EPI>
__device__ void run_gemm(const float* __restrict__ Wg, const float* __restrict__ bias,
                         const float* __restrict__ mrow, const float* __restrict__ mbias,
                         char* sm, float* __restrict__ out, int wt, int h, int tid)
{
    uint4* AFH = (uint4*)(sm + AFH_B);
    uint4* AFL = (uint4*)(sm + AFL_B);
    uint2* BFH = (uint2*)(sm + BFH_B);
    uint2* BFL = (uint2*)(sm + BFL_B);
    float* xbuf  = (float*)(sm + XBUF_B);
    float* sBias = (float*)(sm + SBIAS_B);
    float* sMrow = (float*)(sm + SMROW_B);
    float* sMP   = (float*)(sm + SMP_B);
    float* sAV   = (float*)(sm + SAV_B);
    int*   sAI   = (int*)(sm + SAI_B);

    const int warp = tid >> 5, lane = tid & 31;
    const int mi = warp >> 2, ni = warp & 3;
    const int g = lane >> 2, t = lane & 3;

    // ---- hoisted B loads: pure gmem reads, issue BEFORE the entry barrier so
    // their latency overlaps the prior epilogue's drain ----
    float2 wraw[8][2];
    int ls = tid & 31, ntv = (tid >> 5) & 15;
    int gs = ls >> 2, ts = ls & 3;
    int o = ntv * 8 + gs;
#pragma unroll
    for (int k = 0; k < 8; k++) {
        int c0 = k * 16 + 2 * ts;
        wraw[k][0] = *(const float2*)&Wg[o * 128 + c0];
        wraw[k][1] = *(const float2*)&Wg[o * 128 + c0 + 8];
    }

    __syncthreads();   // prior epilogue A-writes visible; prior B-reads done

    if (tid < 128) sBias[tid] = bias[tid];
    if (EPI == 2 && tid < 128) sMrow[tid] = mrow[tid];

    // ---- stage B into fragment slots, split hi/lo ----
#pragma unroll
    for (int k = 0; k < 8; k++) {
        int s = (k * 16 + ntv) * 32 + ls;    // [ks][nt][lane]
        uint32_t bh0, bl0, bh1, bl1;
        split2(wraw[k][0].x, wraw[k][0].y, bh0, bl0);
        split2(wraw[k][1].x, wraw[k][1].y, bh1, bl1);
        BFH[s] = make_uint2(bh0, bh1);
        BFL[s] = make_uint2(bl0, bl1);
    }
    __syncthreads();

    float acc[2][4][4];
#pragma unroll
    for (int a = 0; a < 2; a++)
#pragma unroll
        for (int b = 0; b < 4; b++)
#pragma unroll
            for (int c = 0; c < 4; c++) acc[a][b][c] = 0.0f;

    // ---- mainloop: 8 k-steps, no syncs ----
    // EPI0 (reg1): 2-term split — drop A_lo term entirely (x_lo·W ~2.4e-4 rel
    // on x_r, attenuated to ~1e-7 at the final output through the regressor).
#pragma unroll
    for (int ks = 0; ks < 8; ks++) {
        uint4 ah[2], al[2];
#pragma unroll
        for (int m2 = 0; m2 < 2; m2++) {
            int s = (ks * 8 + 2 * mi + m2) * 32 + lane;
            ah[m2] = AFH[s];
            if (EPI != 0) al[m2] = AFL[s];
        }
        uint2 bh[4], bl[4];
#pragma unroll
        for (int n4 = 0; n4 < 4; n4++) {
            int s = (ks * 16 + ni * 4 + n4) * 32 + lane;
            bh[n4] = BFH[s];
            bl[n4] = BFL[s];
        }
#pragma unroll
        for (int m2 = 0; m2 < 2; m2++)
#pragma unroll
            for (int n4 = 0; n4 < 4; n4++) {
                float* d = acc[m2][n4];
                if (EPI != 0) mma16(d, al[m2], bh[n4]);   // lo x hi
                mma16(d, ah[m2], bl[n4]);                 // hi x lo
                mma16(d, ah[m2], bh[n4]);                 // hi x hi (largest last)
            }
    }

    // ---------------- epilogue from D fragments ----------------
    // d[j]: R = (2mi+m2)*16 + g + 8*(j>>1), C = (ni*4+n4)*8 + 2t + (j&1)
    if (EPI == 0) {
        // scatter to xbuf[C][132+R]; bank = (8t+g) mod 32 -> conflict-free
#pragma unroll
        for (int m2 = 0; m2 < 2; m2++)
#pragma unroll
            for (int n4 = 0; n4 < 4; n4++)
#pragma unroll
                for (int j = 0; j < 4; j++) {
                    int C = (ni * 4 + n4) * 8 + 2 * t + (j & 1);
                    int R = (2 * mi + m2) * 16 + g + 8 * (j >> 1);
                    xbuf[C * 132 + R] = lrelu(acc[m2][n4][j] + sBias[C]);
                }
        __syncthreads();
        for (int i = tid; i < 4096; i += 512) {
            int c = i >> 5, w4 = (i & 31) << 2;
            *(float4*)&g_xr[(size_t)(h * 128 + c) * W_DIM + wt * 128 + w4] =
                *(float4*)&xbuf[c * 132 + w4];
        }
    } else if (EPI == 1 || EPI == 2) {
        __syncthreads();   // all mainloop A-reads done before overwrite
        float mp[2][2] = {{0.f, 0.f}, {0.f, 0.f}};
#pragma unroll
        for (int m2 = 0; m2 < 2; m2++) {
#pragma unroll
            for (int q = 0; q < 2; q++) {
                float v[2][4];
#pragma unroll
                for (int e = 0; e < 2; e++) {
                    int n4 = 2 * q + e;
#pragma unroll
                    for (int j = 0; j < 4; j++) {
                        int C = (ni * 4 + n4) * 8 + 2 * t + (j & 1);
                        float vv = lrelu(acc[m2][n4][j] + sBias[C]);
                        v[e][j] = vv;
                        if (EPI == 2) mp[m2][j >> 1] = fmaf(vv, sMrow[C], mp[m2][j >> 1]);
                    }
                }
                // thread's own (m2, n4=2q,2q+1) accs form exactly A-slot
                // (ks = 2ni+q, mt = 2mi+m2) at its OWN lane -> conflict-free
                uint32_t h0, l0, h1, l1, h2, l2, h3, l3;
                split2(v[0][0], v[0][1], h0, l0);
                split2(v[0][2], v[0][3], h1, l1);
                split2(v[1][0], v[1][1], h2, l2);
                split2(v[1][2], v[1][3], h3, l3);
                int slot = ((2 * ni + q) * 8 + 2 * mi + m2) * 32 + lane;
                AFH[slot] = make_uint4(h0, h1, h2, h3);
                AFL[slot] = make_uint4(l0, l1, l2, l3);
            }
        }
        if (EPI == 2) {
#pragma unroll
            for (int m2 = 0; m2 < 2; m2++)
#pragma unroll
                for (int rh = 0; rh < 2; rh++) {
                    mp[m2][rh] += __shfl_xor_sync(0xffffffffu, mp[m2][rh], 1);
                    mp[m2][rh] += __shfl_xor_sync(0xffffffffu, mp[m2][rh], 2);
                }
            if (t == 0) {
#pragma unroll
                for (int m2 = 0; m2 < 2; m2++)
#pragma unroll
                    for (int rh = 0; rh < 2; rh++) {
                        int R = (2 * mi + m2) * 16 + g + 8 * rh;
                        sMP[ni * 128 + R] = mp[m2][rh];
                    }
            }
            __syncthreads();
            if (tid < 128) {
                float m = sMP[tid] + sMP[128 + tid] + sMP[256 + tid] + sMP[384 + tid]
                        + __ldg(mbias);
                out[HWTOT + h * W_DIM + wt * 128 + tid] = lrelu(m);
            }
        }
    } else {  // EPI == 3: argmax (first-max-on-tie like jnp.argmax)
#pragma unroll
        for (int m2 = 0; m2 < 2; m2++)
#pragma unroll
            for (int rh = 0; rh < 2; rh++) {
                float bv = -3.4e38f; int bi = 0;
#pragma unroll
                for (int n4 = 0; n4 < 4; n4++)
#pragma unroll
                    for (int jb = 0; jb < 2; jb++) {
                        int C = (ni * 4 + n4) * 8 + 2 * t + jb;
                        float v = acc[m2][n4][rh * 2 + jb] + sBias[C];
                        if (v > bv) { bv = v; bi = C; }
                    }
#pragma unroll
                for (int off = 1; off <= 2; off <<= 1) {
                    float ov = __shfl_xor_sync(0xffffffffu, bv, off);
                    int   oi = __shfl_xor_sync(0xffffffffu, bi, off);
                    if (ov > bv || (ov == bv && oi < bi)) { bv = ov; bi = oi; }
                }
                if (t == 0) {
                    int R = (2 * mi + m2) * 16 + g + 8 * rh;
                    sAV[ni * 128 + R] = bv;
                    sAI[ni * 128 + R] = bi;
                }
            }
        __syncthreads();
        if (tid < 128) {
            float b = sAV[tid]; int x = sAI[tid];
#pragma unroll
            for (int q = 1; q < 4; q++) {
                float ov = sAV[q * 128 + tid];
                int   oi = sAI[q * 128 + tid];
                if (ov > b || (ov == b && oi < x)) { b = ov; x = oi; }
            }
            g_inds[h * W_DIM + wt * 128 + tid] = x;
        }
    }
}

// K1: per (wtile, h): x -> A-frags, then reg1, cl1, cl2(+mask), cl3(+argmax)
__global__ void __launch_bounds__(512, 1)
k1_kernel(const float* __restrict__ x_in,
          const float* __restrict__ w_cl1, const float* __restrict__ b_cl1,
          const float* __restrict__ w_cl2, const float* __restrict__ b_cl2,
          const float* __restrict__ w_cl3, const float* __restrict__ b_cl3,
          const float* __restrict__ w_reg1, const float* __restrict__ b_reg1,
          float* __restrict__ out)
{
    extern __shared__ char sm[];
    float* xbuf = (float*)(sm + XBUF_B);
    uint4* AFH = (uint4*)(sm + AFH_B);
    uint4* AFL = (uint4*)(sm + AFL_B);
    const int tid = threadIdx.x;
    const int wt = blockIdx.x, h = blockIdx.y;

    // coalesced x load into bounce buffer [c][w]
    const float* xsrc = x_in + (size_t)h * W_DIM + wt * 128;
    for (int i = tid; i < 4096; i += 512) {
        int c = i >> 5, w4 = (i & 31) << 2;
        *(float4*)&xbuf[c * 132 + w4] = *(const float4*)&xsrc[(size_t)c * HWTOT + w4];
    }
    __syncthreads();

    // restage into A-fragment slots (thread builds whole uint4 slots: both
    // reads and STS.128 writes conflict-free)
#pragma unroll
    for (int k = 0; k < 4; k++) {
        int s = tid + 512 * k;
        int ls = s & 31, mt = (s >> 5) & 7, ks = s >> 8;
        int gs = ls >> 2, ts = ls & 3;
        int R0 = mt * 16 + gs, C0 = ks * 16 + 2 * ts;
        float v00 = xbuf[(C0 + 0) * 132 + R0],     v01 = xbuf[(C0 + 1) * 132 + R0];
        float v10 = xbuf[(C0 + 0) * 132 + R0 + 8], v11 = xbuf[(C0 + 1) * 132 + R0 + 8];
        float v02 = xbuf[(C0 + 8) * 132 + R0],     v03 = xbuf[(C0 + 9) * 132 + R0];
        float v12 = xbuf[(C0 + 8) * 132 + R0 + 8], v13 = xbuf[(C0 + 9) * 132 + R0 + 8];
        uint32_t h0, l0, h1, l1, h2, l2, h3, l3;
        split2(v00, v01, h0, l0);
        split2(v10, v11, h1, l1);
        split2(v02, v03, h2, l2);
        split2(v12, v13, h3, l3);
        AFH[s] = make_uint4(h0, h1, h2, h3);
        AFL[s] = make_uint4(l0, l1, l2, l3);
    }

    run_gemm<0>(w_reg1 + h * 16384, b_reg1 + h * 128, nullptr, nullptr,
                sm, out, wt, h, tid);
    run_gemm<1>(w_cl1 + h * 16384, b_cl1 + h * 128, nullptr, nullptr,
                sm, out, wt, h, tid);
    run_gemm<2>(w_cl2 + h * 16384, b_cl2 + h * 128,
                w_cl3 + h * 16512 + 16384, b_cl3 + h * 129 + 128,
                sm, out, wt, h, tid);
    run_gemm<3>(w_cl3 + h * 16512, b_cl3 + h * 129, nullptr, nullptr,
                sm, out, wt, h, tid);
}

// K2: gathered regressor head + final output. 4 pixels per warp:
// lane = 8*p + cg; pixel p handles channel set c = 8j + cg (j=0..15).
// w2 reads stay 128B-coalesced per pixel; 16 independent LDG.128 in flight
// per lane; reduction = 3 shfl rounds for all 4 pixels at once.
// Cross-pixel pairing per reference: pixel (h,w) uses w2[inds_r[n]],
// n = w*448 + h, but its OWN x_r row and OWN argmax in the final sum.
__global__ void __launch_bounds__(512)
k2_kernel(const float* __restrict__ w2, const float* __restrict__ b2,
          const float* __restrict__ w3, const float* __restrict__ b3,
          float* __restrict__ out)
{
    extern __shared__ float smem[];
    float* sxr    = smem;                    // [128 w][129] (c contiguous per pixel)
    int*   s_indr = (int*)(smem + 16512);    // 128
    int*   s_self = (int*)(smem + 16512 + 128);

    const int tid = threadIdx.x;
    const int wt = blockIdx.x, h = blockIdx.y;

    // conflict-free transpose load: lane owns pixel w, iterates channels
    for (int i = tid; i < 16384; i += 512) {
        int c = i >> 7, w = i & 127;
        sxr[w * 129 + c] = g_xr[(size_t)(h * 128 + c) * W_DIM + wt * 128 + w];
    }
    if (tid < 128) {
        int wg = wt * 128 + tid;
        int n = wg * H_DIM + h;                  // flattening order (w,h)
        s_indr[tid] = g_inds[n] + (n >> 9) * 128;
        s_self[tid] = g_inds[h * W_DIM + wg];
    }
    __syncthreads();

    const int warp = tid >> 5, lane = tid & 31;
    const int p = lane >> 3, cg = lane & 7;

#pragma unroll
    for (int it = 0; it < 2; it++) {
        const int wloc = warp * 8 + it * 4 + p;
        const int ind_r = s_indr[wloc];
        const float4* w2p = (const float4*)w2 + (size_t)ind_r * 128;

        // 16 independent coalesced loads (per j: 8 lanes x 16B = 128B/pixel)
        float4 q[16];
#pragma unroll
        for (int j = 0; j < 16; j++) q[j] = w2p[8 * j + cg];

        float ax = 0.f, ay = 0.f, az = 0.f, aw = 0.f;
#pragma unroll
        for (int j = 0; j < 16; j++) {
            float xv = sxr[wloc * 129 + 8 * j + cg];
            ax = fmaf(xv, q[j].x, ax);
            ay = fmaf(xv, q[j].y, ay);
            az = fmaf(xv, q[j].z, az);
            aw = fmaf(xv, q[j].w, aw);
        }
        // reduce across the 8 lanes of each pixel group (offsets 1,2,4)
#pragma unroll
        for (int off = 1; off <= 4; off <<= 1) {
            ax += __shfl_xor_sync(0xffffffffu, ax, off);
            ay += __shfl_xor_sync(0xffffffffu, ay, off);
            az += __shfl_xor_sync(0xffffffffu, az, off);
            aw += __shfl_xor_sync(0xffffffffu, aw, off);
        }
        if (cg == 0) {
            float4 b2v = *(const float4*)&b2[ind_r * 4];
            float h0 = lrelu(ax + b2v.x);
            float h1 = lrelu(ay + b2v.y);
            float h2 = lrelu(az + b2v.z);
            float h3 = lrelu(aw + b2v.w);
            float4 w3v = *(const float4*)&w3[ind_r * 4];
            float r = fmaf(h0, w3v.x, fmaf(h1, w3v.y, fmaf(h2, w3v.z,
                      fmaf(h3, w3v.w, b3[ind_r]))));
            out[h * W_DIM + wt * 128 + wloc] =
                ((float)s_self[wloc] + r) * (1.0f / 128.0f);
        }
    }
}

extern "C" void kernel_launch(void* const* d_in, const int* in_sizes, int n_in,
                              void* d_out, int out_size)
{
    const float* x_in   = (const float*)d_in[0];
    const float* w_cl1  = (const float*)d_in[1];
    const float* b_cl1  = (const float*)d_in[2];
    const float* w_cl2  = (const float*)d_in[3];
    const float* b_cl2  = (const float*)d_in[4];
    const float* w_cl3  = (const float*)d_in[5];
    const float* b_cl3  = (const float*)d_in[6];
    const float* w_reg1 = (const float*)d_in[7];
    const float* b_reg1 = (const float*)d_in[8];
    const float* w2     = (const float*)d_in[9];
    const float* b2     = (const float*)d_in[10];
    const float* w3     = (const float*)d_in[11];
    const float* b3     = (const float*)d_in[12];
    float* out = (float*)d_out;

    const int smem2 = (16512 + 256) * 4;
    cudaFuncSetAttribute(k1_kernel, cudaFuncAttributeMaxDynamicSharedMemorySize, SMEM1_B);
    cudaFuncSetAttribute(k2_kernel, cudaFuncAttributeMaxDynamicSharedMemorySize, smem2);

    dim3 grid(4, H_DIM);
    k1_kernel<<<grid, 512, SMEM1_B>>>(x_in, w_cl1, b_cl1, w_cl2, b_cl2,
                                      w_cl3, b_cl3, w_reg1, b_reg1, out);
    k2_kernel<<<grid, 512, smem2>>>(w2, b2, w3, b3, out);
}